// round 1
// baseline (speedup 1.0000x reference)
#include <cuda_runtime.h>
#include <math.h>

#define BB 4
#define NN_ 1024
#define DIM 256
#define HEADS 4
#define DH 64
#define DEPTH 4
#define MLP 1024
#define EPS 1e-5f
#define SCALE 0.0625f   // DIM^-0.5

// ---------------- scratch (static device globals; no runtime alloc) ----------------
__device__ float g_x  [BB*NN_*DIM];          // current residual stream x
__device__ float g_xn [BB*NN_*DIM];          // GX / xn / xn2 temp
__device__ float g_xma[BB*NN_*DIM];          // x_ma (pre/post LN+relu)
__device__ float g_q  [BB*NN_*DIM];
__device__ float g_kv [BB*NN_*2*DIM];        // k = cols [0,256), v = cols [256,512)
__device__ float g_ao [BB*NN_*DIM];          // attention output (heads concatenated)
__device__ float g_G  [(long)BB*NN_*NN_];          // 16 MiB
__device__ float g_bias[(long)BB*HEADS*NN_*NN_];   // add_attn, 64 MiB
__device__ float g_dots[(long)BB*HEADS*NN_*NN_];   // scores / probs, 64 MiB
__device__ float g_ff [BB*NN_*MLP];                // 16 MiB

// ---------------- reductions ----------------
__device__ __forceinline__ float warp_sum(float v) {
#pragma unroll
    for (int o = 16; o; o >>= 1) v += __shfl_xor_sync(0xffffffffu, v, o);
    return v;
}
__device__ __forceinline__ float warp_max(float v) {
#pragma unroll
    for (int o = 16; o; o >>= 1) v = fmaxf(v, __shfl_xor_sync(0xffffffffu, v, o));
    return v;
}
// blockDim.x == 256
__device__ __forceinline__ float block_sum(float v, float* sh) {
    int lane = threadIdx.x & 31, w = threadIdx.x >> 5;
    v = warp_sum(v);
    if (lane == 0) sh[w] = v;
    __syncthreads();
    v = (lane < 8) ? sh[lane] : 0.0f;
    v = warp_sum(v);
    __syncthreads();
    return v;
}
__device__ __forceinline__ float block_max(float v, float* sh) {
    int lane = threadIdx.x & 31, w = threadIdx.x >> 5;
    v = warp_max(v);
    if (lane == 0) sh[w] = v;
    __syncthreads();
    v = (lane < 8) ? sh[lane] : -INFINITY;
    v = warp_max(v);
    __syncthreads();
    return v;
}

// ---------------- generic fp32 GEMM: 64x64 tile, BK=16, 4x4 microtile ----------------
// C[M,Nc] = op(A[M,K]) * op(B) with optional epilogue.
// EPI: 0 = plain, 1 = acc*alpha + E[row,col] (bias matrix), 2 = acc + E[row,col] + bv[col],
//      3 = gelu(acc + bv[col])
// TRANSB: B is [Nc,K] row-major (access B^T).
// batch: z = blockIdx.z; zb = z/Hn, zh = z%Hn; operand offset = zb*Xb + zh*Xh.
template <int EPI, bool TRANSB>
__global__ __launch_bounds__(256)
void gemm_k(const float* __restrict__ A, const float* __restrict__ Bm,
            float* __restrict__ C, const float* __restrict__ E,
            const float* __restrict__ bv,
            int K, int lda, int ldb, int ldc,
            long Ab, long Ah, long Bb, long Bh, long Cb, long Ch,
            int Hn, float alpha) {
    __shared__ float As[16 * 68];
    __shared__ float Bs[16 * 68];

    int z = blockIdx.z;
    int zb = z / Hn, zh = z % Hn;
    A  += zb * Ab + zh * Ah;
    Bm += zb * Bb + zh * Bh;
    long co = zb * Cb + zh * Ch;
    C += co;
    if (EPI == 1 || EPI == 2) E += co;

    int tid = threadIdx.x;
    int tx = tid & 15, ty = tid >> 4;
    int row0 = blockIdx.y * 64, col0 = blockIdx.x * 64;

    float acc[4][4] = {};

    for (int k0 = 0; k0 < K; k0 += 16) {
#pragma unroll
        for (int i = 0; i < 4; i++) {
            int idx = tid + i * 256;
            int kk = idx & 15, mm = idx >> 4;
            As[kk * 68 + mm] = A[(long)(row0 + mm) * lda + (k0 + kk)];
        }
#pragma unroll
        for (int i = 0; i < 4; i++) {
            int idx = tid + i * 256;
            if (!TRANSB) {
                int nn = idx & 63, kk = idx >> 6;
                Bs[kk * 68 + nn] = Bm[(long)(k0 + kk) * ldb + (col0 + nn)];
            } else {
                int kk = idx & 15, nn = idx >> 4;
                Bs[kk * 68 + nn] = Bm[(long)(col0 + nn) * ldb + (k0 + kk)];
            }
        }
        __syncthreads();
#pragma unroll
        for (int kk = 0; kk < 16; kk++) {
            float4 av = *(const float4*)(As + kk * 68 + ty * 4);
            float4 bw = *(const float4*)(Bs + kk * 68 + tx * 4);
            float a4[4] = {av.x, av.y, av.z, av.w};
            float b4[4] = {bw.x, bw.y, bw.z, bw.w};
#pragma unroll
            for (int i = 0; i < 4; i++)
#pragma unroll
                for (int j = 0; j < 4; j++) acc[i][j] += a4[i] * b4[j];
        }
        __syncthreads();
    }

#pragma unroll
    for (int i = 0; i < 4; i++) {
        int r = row0 + ty * 4 + i;
#pragma unroll
        for (int j = 0; j < 4; j++) {
            int c = col0 + tx * 4 + j;
            long off = (long)r * ldc + c;
            float v = acc[i][j];
            if (EPI == 1) v = v * alpha + E[off];
            else if (EPI == 2) v = v + E[off] + bv[c];
            else if (EPI == 3) { v += bv[c]; v = 0.5f * v * (1.0f + erff(v * 0.70710678118654752f)); }
            C[off] = v;
        }
    }
}

// ---------------- prep: add_attn = b0+b1 ; G = softmax(mean_h(b0) * mean_h(b1), axis=j) ----------
__global__ __launch_bounds__(256)
void prep_kernel(const float* __restrict__ ab) {
    __shared__ float sh[32];
    int b = blockIdx.x >> 10;
    int i = blockIdx.x & 1023;
    const long BHNN = (long)BB * HEADS * NN_ * NN_;
    int tid = threadIdx.x;
    float val[4];
#pragma unroll
    for (int t = 0; t < 4; t++) {
        int j = tid + t * 256;
        float sa = 0.0f, sb = 0.0f;
#pragma unroll
        for (int h = 0; h < HEADS; h++) {
            long o = (((long)(b * HEADS + h) * NN_) + i) * NN_ + j;
            float a0 = ab[o];
            float a1 = ab[BHNN + o];
            sa += a0; sb += a1;
            g_bias[o] = a0 + a1;
        }
        val[t] = (sa * 0.25f) * (sb * 0.25f);
    }
    float m = fmaxf(fmaxf(val[0], val[1]), fmaxf(val[2], val[3]));
    m = block_max(m, sh);
    float s = 0.0f;
#pragma unroll
    for (int t = 0; t < 4; t++) { val[t] = __expf(val[t] - m); s += val[t]; }
    s = block_sum(s, sh);
    float inv = 1.0f / s;
    long rowo = ((long)(b * NN_ + i)) * NN_;
#pragma unroll
    for (int t = 0; t < 4; t++) g_G[rowo + tid + t * 256] = val[t] * inv;
}

// ---------------- row softmax over N for dots (in-place) ----------------
__global__ __launch_bounds__(256)
void softmax_kernel(float* __restrict__ d) {
    __shared__ float sh[32];
    float* p = d + (long)blockIdx.x * NN_;
    int tid = threadIdx.x;
    float val[4];
#pragma unroll
    for (int t = 0; t < 4; t++) val[t] = p[tid + t * 256];
    float m = fmaxf(fmaxf(val[0], val[1]), fmaxf(val[2], val[3]));
    m = block_max(m, sh);
    float s = 0.0f;
#pragma unroll
    for (int t = 0; t < 4; t++) { val[t] = __expf(val[t] - m); s += val[t]; }
    s = block_sum(s, sh);
    float inv = 1.0f / s;
#pragma unroll
    for (int t = 0; t < 4; t++) p[tid + t * 256] = val[t] * inv;
}

// ---------------- LayerNorm over DIM=256 (one block per row), optional relu ----------------
__global__ __launch_bounds__(256)
void ln_kernel(const float* __restrict__ in, float* __restrict__ out,
               const float* __restrict__ g, const float* __restrict__ bt, int relu) {
    __shared__ float sh[32];
    long row = blockIdx.x;
    int c = threadIdx.x;
    float v = in[row * DIM + c];
    float mean = block_sum(v, sh) * (1.0f / DIM);
    float d = v - mean;
    float var = block_sum(d * d, sh) * (1.0f / DIM);
    float o = d * rsqrtf(var + EPS) * g[c] + bt[c];
    if (relu) o = fmaxf(o, 0.0f);
    out[row * DIM + c] = o;
}

__global__ void copy_kernel(const float* __restrict__ in, float* __restrict__ out, int n) {
    int i = blockIdx.x * blockDim.x + threadIdx.x;
    if (i < n) out[i] = in[i];
}

// ---------------- host ----------------
extern "C" void kernel_launch(void* const* d_in, const int* in_sizes, int n_in,
                              void* d_out, int out_size) {
    const float* x_in   = (const float*)d_in[0];
    const float* abias  = (const float*)d_in[1];
    const float* ln1_g  = (const float*)d_in[2];
    const float* ln1_b  = (const float*)d_in[3];
    const float* Wkv    = (const float*)d_in[4];
    const float* Wq     = (const float*)d_in[5];
    const float* Wo     = (const float*)d_in[6];
    const float* bo     = (const float*)d_in[7];
    const float* ln2_g  = (const float*)d_in[8];
    const float* ln2_b  = (const float*)d_in[9];
    const float* W1     = (const float*)d_in[10];
    const float* b1     = (const float*)d_in[11];
    const float* W2     = (const float*)d_in[12];
    const float* b2     = (const float*)d_in[13];
    const float* Wg     = (const float*)d_in[14];
    const float* lng_g  = (const float*)d_in[15];
    const float* lng_b  = (const float*)d_in[16];
    float* out = (float*)d_out;

    float *px, *pxn, *pxma, *pq, *pkv, *pao, *pG, *pbias, *pdots, *pff;
    cudaGetSymbolAddress((void**)&px, g_x);
    cudaGetSymbolAddress((void**)&pxn, g_xn);
    cudaGetSymbolAddress((void**)&pxma, g_xma);
    cudaGetSymbolAddress((void**)&pq, g_q);
    cudaGetSymbolAddress((void**)&pkv, g_kv);
    cudaGetSymbolAddress((void**)&pao, g_ao);
    cudaGetSymbolAddress((void**)&pG, g_G);
    cudaGetSymbolAddress((void**)&pbias, g_bias);
    cudaGetSymbolAddress((void**)&pdots, g_dots);
    cudaGetSymbolAddress((void**)&pff, g_ff);

    const int ROWS = BB * NN_;           // 4096
    const long ND = (long)NN_ * DIM;     // per-batch x stride
    dim3 blk(256);

    prep_kernel<<<BB * NN_, blk>>>(abias);
    copy_kernel<<<(ROWS * DIM + 255) / 256, blk>>>(x_in, px, ROWS * DIM);

    for (int l = 0; l < DEPTH; l++) {
        // GX = G @ x  -> g_xn          [per b: 1024x256, K=1024]
        gemm_k<0, false><<<dim3(DIM / 64, NN_ / 64, BB), blk>>>(
            pG, px, pxn, nullptr, nullptr,
            NN_, NN_, DIM, DIM,
            (long)NN_ * NN_, 0, ND, 0, ND, 0, 1, 1.0f);
        // x_ma_pre = GX @ Wg -> g_xma  [4096x256, K=256]
        gemm_k<0, false><<<dim3(DIM / 64, ROWS / 64, 1), blk>>>(
            pxn, Wg, pxma, nullptr, nullptr,
            DIM, DIM, DIM, DIM, 0, 0, 0, 0, 0, 0, 1, 1.0f);
        // x_ma = relu(LN(x_ma_pre))  (in place)
        ln_kernel<<<ROWS, DIM>>>(pxma, pxma, lng_g, lng_b, 1);
        // xn = LN(x) -> g_xn
        ln_kernel<<<ROWS, DIM>>>(px, pxn, ln1_g + l * DIM, ln1_b + l * DIM, 0);
        // kv = xn @ Wkv[l] -> g_kv [4096x512]
        gemm_k<0, false><<<dim3(2 * DIM / 64, ROWS / 64, 1), blk>>>(
            pxn, Wkv + (long)l * DIM * 2 * DIM, pkv, nullptr, nullptr,
            DIM, DIM, 2 * DIM, 2 * DIM, 0, 0, 0, 0, 0, 0, 1, 1.0f);
        // q = x_ma @ Wq[l] -> g_q [4096x256]
        gemm_k<0, false><<<dim3(DIM / 64, ROWS / 64, 1), blk>>>(
            pxma, Wq + (long)l * DIM * DIM, pq, nullptr, nullptr,
            DIM, DIM, DIM, DIM, 0, 0, 0, 0, 0, 0, 1, 1.0f);
        // dots = q_h @ k_h^T * scale + add_attn   [per (b,h): 1024x1024, K=64]
        gemm_k<1, true><<<dim3(NN_ / 64, NN_ / 64, BB * HEADS), blk>>>(
            pq, pkv, pdots, pbias, nullptr,
            DH, DIM, 2 * DIM, NN_,
            ND, DH, (long)NN_ * 2 * DIM, DH,
            (long)HEADS * NN_ * NN_, (long)NN_ * NN_, HEADS, SCALE);
        // softmax rows
        softmax_kernel<<<BB * HEADS * NN_, blk>>>(pdots);
        // out_h = attn @ v_h -> g_ao (heads concat) [per (b,h): 1024x64, K=1024]
        gemm_k<0, false><<<dim3(DH / 64, NN_ / 64, BB * HEADS), blk>>>(
            pdots, pkv + DIM, pao, nullptr, nullptr,
            NN_, NN_, 2 * DIM, DIM,
            (long)HEADS * NN_ * NN_, (long)NN_ * NN_,
            (long)NN_ * 2 * DIM, DH, ND, DH, HEADS, 1.0f);
        // x = x + out @ Wo[l] + bo[l]
        gemm_k<2, false><<<dim3(DIM / 64, ROWS / 64, 1), blk>>>(
            pao, Wo + (long)l * DIM * DIM, px, px, bo + l * DIM,
            DIM, DIM, DIM, DIM, 0, 0, 0, 0, 0, 0, 1, 1.0f);
        // xn2 = LN(x) -> g_xn
        ln_kernel<<<ROWS, DIM>>>(px, pxn, ln2_g + l * DIM, ln2_b + l * DIM, 0);
        // ff = gelu(xn2 @ W1[l] + b1[l]) -> g_ff [4096x1024]
        gemm_k<3, false><<<dim3(MLP / 64, ROWS / 64, 1), blk>>>(
            pxn, W1 + (long)l * DIM * MLP, pff, nullptr, b1 + l * MLP,
            DIM, DIM, MLP, MLP, 0, 0, 0, 0, 0, 0, 1, 1.0f);
        // x = x + ff @ W2[l] + b2[l]
        gemm_k<2, false><<<dim3(DIM / 64, ROWS / 64, 1), blk>>>(
            pff, W2 + (long)l * MLP * DIM, px, px, b2 + l * DIM,
            MLP, MLP, DIM, DIM, 0, 0, 0, 0, 0, 0, 1, 1.0f);
    }

    copy_kernel<<<(ROWS * DIM + 255) / 256, blk>>>(px, out, ROWS * DIM);
}

// round 2
// speedup vs baseline: 1.8995x; 1.8995x over previous
#include <cuda_runtime.h>
#include <math.h>
#include <stdint.h>

#define BB 4
#define NN_ 1024
#define DIM 256
#define HEADS 4
#define DH 64
#define DEPTH 4
#define MLP 1024
#define EPS 1e-5f
#define SCALE 0.0625f   // DIM^-0.5

// ---------------- scratch (static device globals; no runtime alloc) ----------------
__device__ float g_x  [BB*NN_*DIM];
__device__ float g_xn [BB*NN_*DIM];
__device__ float g_xma[BB*NN_*DIM];
__device__ float g_q  [BB*NN_*DIM];
__device__ float g_kv [BB*NN_*2*DIM];
__device__ float g_ao [BB*NN_*DIM];
__device__ float g_G  [(long)BB*NN_*NN_];
__device__ float g_bias[(long)BB*HEADS*NN_*NN_];
__device__ float g_dots[(long)BB*HEADS*NN_*NN_];
__device__ float g_ff [BB*NN_*MLP];

// ---------------- reductions ----------------
__device__ __forceinline__ float warp_sum(float v) {
#pragma unroll
    for (int o = 16; o; o >>= 1) v += __shfl_xor_sync(0xffffffffu, v, o);
    return v;
}
__device__ __forceinline__ float warp_max(float v) {
#pragma unroll
    for (int o = 16; o; o >>= 1) v = fmaxf(v, __shfl_xor_sync(0xffffffffu, v, o));
    return v;
}
__device__ __forceinline__ float block_sum(float v, float* sh) {
    int lane = threadIdx.x & 31, w = threadIdx.x >> 5;
    v = warp_sum(v);
    if (lane == 0) sh[w] = v;
    __syncthreads();
    v = (lane < 8) ? sh[lane] : 0.0f;
    v = warp_sum(v);
    __syncthreads();
    return v;
}
__device__ __forceinline__ float block_max(float v, float* sh) {
    int lane = threadIdx.x & 31, w = threadIdx.x >> 5;
    v = warp_max(v);
    if (lane == 0) sh[w] = v;
    __syncthreads();
    v = (lane < 8) ? sh[lane] : -INFINITY;
    v = warp_max(v);
    __syncthreads();
    return v;
}

// ---------------- tf32 helpers ----------------
__device__ __forceinline__ uint32_t f2tf(float f) {
    uint32_t u;
    asm("cvt.rna.tf32.f32 %0, %1;" : "=r"(u) : "f"(f));
    return u;
}
__device__ __forceinline__ void mma_tf32(float c[4], const uint32_t a[4], const uint32_t b[2]) {
    asm volatile(
        "mma.sync.aligned.m16n8k8.row.col.f32.tf32.tf32.f32 "
        "{%0,%1,%2,%3}, {%4,%5,%6,%7}, {%8,%9}, {%0,%1,%2,%3};"
        : "+f"(c[0]), "+f"(c[1]), "+f"(c[2]), "+f"(c[3])
        : "r"(a[0]), "r"(a[1]), "r"(a[2]), "r"(a[3]), "r"(b[0]), "r"(b[1]));
}

// ---------------- tensor-core GEMM: C = op(A)*op(B), tf32 mma, fp32 accum ----------------
// EPI: 0 plain, 1 acc*alpha + E, 2 acc + E + bv[col], 3 gelu(acc + bv[col])
// TRANSB: B stored [Nc,K] row-major (use B^T).
// batch: z -> zb=z/Hn, zh=z%Hn; operand offset = zb*Xb + zh*Xh.
// 256 threads = 8 warps. Warp tile WM x WN; (BM/WM)*(BN/WN) must be 8. BK=16.
template <int BM, int BN, int WM, int WN, int EPI, bool TRANSB>
__global__ __launch_bounds__(256, 2)
void mma_gemm(const float* __restrict__ A, const float* __restrict__ Bm,
              float* __restrict__ C, const float* __restrict__ E,
              const float* __restrict__ bv,
              int K, int lda, int ldb, int ldc,
              long Ab, long Ah, long Bb, long Bh, long Cb, long Ch,
              int Hn, float alpha) {
    constexpr int LDSA = BM + 8;            // stride % 32 == 8 -> conflict-free frags
    constexpr int LDSB = BN + 8;
    constexpr int AF4 = BM / 64;            // float4 loads per thread per tile
    constexpr int BF4 = BN / 64;
    constexpr int BNQ = BN / 4;
    constexpr int WARPS_N = BN / WN;
    constexpr int MT = WM / 16, NT = WN / 8;

    __shared__ __align__(16) uint32_t As[2][16 * LDSA];
    __shared__ __align__(16) uint32_t Bs[2][16 * LDSB];

    int z = blockIdx.z, zb = z / Hn, zh = z % Hn;
    A  += zb * Ab + zh * Ah;
    Bm += zb * Bb + zh * Bh;
    long co = zb * Cb + zh * Ch;
    C += co;
    if (EPI == 1 || EPI == 2) E += co;

    const int tid = threadIdx.x;
    const int wid = tid >> 5, lane = tid & 31;
    const int gid = lane >> 2, tg = lane & 3;
    const int wm0 = (wid / WARPS_N) * WM;
    const int wn0 = (wid % WARPS_N) * WN;
    const int row0 = blockIdx.y * BM, col0 = blockIdx.x * BN;

    float acc[MT][NT][4];
#pragma unroll
    for (int i = 0; i < MT; i++)
#pragma unroll
        for (int j = 0; j < NT; j++)
#pragma unroll
            for (int k = 0; k < 4; k++) acc[i][j][k] = 0.0f;

    float4 ra[AF4], rb[BF4];

    auto ldg_tile = [&](int k0) {
#pragma unroll
        for (int i = 0; i < AF4; i++) {
            int q = tid + i * 256;
            int m = q >> 2, kq = q & 3;
            ra[i] = *(const float4*)(A + (long)(row0 + m) * lda + k0 + 4 * kq);
        }
#pragma unroll
        for (int i = 0; i < BF4; i++) {
            int q = tid + i * 256;
            if (!TRANSB) {
                int kk = q / BNQ, nq = q % BNQ;
                rb[i] = *(const float4*)(Bm + (long)(k0 + kk) * ldb + col0 + 4 * nq);
            } else {
                int n = q >> 2, kq = q & 3;
                rb[i] = *(const float4*)(Bm + (long)(col0 + n) * ldb + k0 + 4 * kq);
            }
        }
    };
    auto sts_tile = [&](int buf) {
#pragma unroll
        for (int i = 0; i < AF4; i++) {
            int q = tid + i * 256;
            int m = q >> 2, kq = q & 3;
            uint32_t* p = As[buf];
            p[(4 * kq + 0) * LDSA + m] = f2tf(ra[i].x);
            p[(4 * kq + 1) * LDSA + m] = f2tf(ra[i].y);
            p[(4 * kq + 2) * LDSA + m] = f2tf(ra[i].z);
            p[(4 * kq + 3) * LDSA + m] = f2tf(ra[i].w);
        }
#pragma unroll
        for (int i = 0; i < BF4; i++) {
            int q = tid + i * 256;
            uint32_t* p = Bs[buf];
            if (!TRANSB) {
                int kk = q / BNQ, nq = q % BNQ;
                uint4 v;
                v.x = f2tf(rb[i].x); v.y = f2tf(rb[i].y);
                v.z = f2tf(rb[i].z); v.w = f2tf(rb[i].w);
                *(uint4*)(p + kk * LDSB + 4 * nq) = v;
            } else {
                int n = q >> 2, kq = q & 3;
                p[(4 * kq + 0) * LDSB + n] = f2tf(rb[i].x);
                p[(4 * kq + 1) * LDSB + n] = f2tf(rb[i].y);
                p[(4 * kq + 2) * LDSB + n] = f2tf(rb[i].z);
                p[(4 * kq + 3) * LDSB + n] = f2tf(rb[i].w);
            }
        }
    };
    auto compute = [&](int buf) {
#pragma unroll
        for (int ks = 0; ks < 16; ks += 8) {
            uint32_t af[MT][4], bf[NT][2];
#pragma unroll
            for (int mt = 0; mt < MT; mt++) {
                const uint32_t* p = &As[buf][(ks + tg) * LDSA + wm0 + mt * 16 + gid];
                af[mt][0] = p[0];
                af[mt][1] = p[8];
                af[mt][2] = p[4 * LDSA];
                af[mt][3] = p[4 * LDSA + 8];
            }
#pragma unroll
            for (int nt = 0; nt < NT; nt++) {
                const uint32_t* p = &Bs[buf][(ks + tg) * LDSB + wn0 + nt * 8 + gid];
                bf[nt][0] = p[0];
                bf[nt][1] = p[4 * LDSB];
            }
#pragma unroll
            for (int mt = 0; mt < MT; mt++)
#pragma unroll
                for (int nt = 0; nt < NT; nt++)
                    mma_tf32(acc[mt][nt], af[mt], bf[nt]);
        }
    };

    const int TILES = K / 16;
    ldg_tile(0);
    sts_tile(0);
    __syncthreads();
    for (int t = 0; t < TILES; t++) {
        int cur = t & 1;
        if (t + 1 < TILES) ldg_tile((t + 1) * 16);
        compute(cur);
        if (t + 1 < TILES) sts_tile(cur ^ 1);
        __syncthreads();
    }

    // epilogue: float2 stores (c0/c1 and c2/c3 are column-adjacent)
#pragma unroll
    for (int mt = 0; mt < MT; mt++)
#pragma unroll
        for (int nt = 0; nt < NT; nt++)
#pragma unroll
            for (int half = 0; half < 2; half++) {
                int r = row0 + wm0 + mt * 16 + gid + half * 8;
                int c = col0 + wn0 + nt * 8 + 2 * tg;
                long off = (long)r * ldc + c;
                float v0 = acc[mt][nt][half * 2 + 0];
                float v1 = acc[mt][nt][half * 2 + 1];
                if (EPI == 1) {
                    float2 e = *(const float2*)(E + off);
                    v0 = v0 * alpha + e.x;
                    v1 = v1 * alpha + e.y;
                } else if (EPI == 2) {
                    float2 e = *(const float2*)(E + off);
                    v0 += e.x + bv[c];
                    v1 += e.y + bv[c + 1];
                } else if (EPI == 3) {
                    v0 += bv[c];
                    v1 += bv[c + 1];
                    v0 = 0.5f * v0 * (1.0f + erff(v0 * 0.70710678118654752f));
                    v1 = 0.5f * v1 * (1.0f + erff(v1 * 0.70710678118654752f));
                }
                float2 o; o.x = v0; o.y = v1;
                *(float2*)(C + off) = o;
            }
}

// ---------------- prep: add_attn = b0+b1 ; G = softmax(mean_h(b0)*mean_h(b1), axis=j) ----------
__global__ __launch_bounds__(256)
void prep_kernel(const float* __restrict__ ab) {
    __shared__ float sh[32];
    int b = blockIdx.x >> 10;
    int i = blockIdx.x & 1023;
    const long BHNN = (long)BB * HEADS * NN_ * NN_;
    int tid = threadIdx.x;
    float val[4];
#pragma unroll
    for (int t = 0; t < 4; t++) {
        int j = tid + t * 256;
        float sa = 0.0f, sb = 0.0f;
#pragma unroll
        for (int h = 0; h < HEADS; h++) {
            long o = (((long)(b * HEADS + h) * NN_) + i) * NN_ + j;
            float a0 = ab[o];
            float a1 = ab[BHNN + o];
            sa += a0; sb += a1;
            g_bias[o] = a0 + a1;
        }
        val[t] = (sa * 0.25f) * (sb * 0.25f);
    }
    float m = fmaxf(fmaxf(val[0], val[1]), fmaxf(val[2], val[3]));
    m = block_max(m, sh);
    float s = 0.0f;
#pragma unroll
    for (int t = 0; t < 4; t++) { val[t] = __expf(val[t] - m); s += val[t]; }
    s = block_sum(s, sh);
    float inv = 1.0f / s;
    long rowo = ((long)(b * NN_ + i)) * NN_;
#pragma unroll
    for (int t = 0; t < 4; t++) g_G[rowo + tid + t * 256] = val[t] * inv;
}

// ---------------- row softmax over N for dots (in-place) ----------------
__global__ __launch_bounds__(256)
void softmax_kernel(float* __restrict__ d) {
    __shared__ float sh[32];
    float* p = d + (long)blockIdx.x * NN_;
    int tid = threadIdx.x;
    float val[4];
#pragma unroll
    for (int t = 0; t < 4; t++) val[t] = p[tid + t * 256];
    float m = fmaxf(fmaxf(val[0], val[1]), fmaxf(val[2], val[3]));
    m = block_max(m, sh);
    float s = 0.0f;
#pragma unroll
    for (int t = 0; t < 4; t++) { val[t] = __expf(val[t] - m); s += val[t]; }
    s = block_sum(s, sh);
    float inv = 1.0f / s;
#pragma unroll
    for (int t = 0; t < 4; t++) p[tid + t * 256] = val[t] * inv;
}

// ---------------- LayerNorm over DIM=256 (one block per row), optional relu ----------------
__global__ __launch_bounds__(256)
void ln_kernel(const float* __restrict__ in, float* __restrict__ out,
               const float* __restrict__ g, const float* __restrict__ bt, int relu) {
    __shared__ float sh[32];
    long row = blockIdx.x;
    int c = threadIdx.x;
    float v = in[row * DIM + c];
    float mean = block_sum(v, sh) * (1.0f / DIM);
    float d = v - mean;
    float var = block_sum(d * d, sh) * (1.0f / DIM);
    float o = d * rsqrtf(var + EPS) * g[c] + bt[c];
    if (relu) o = fmaxf(o, 0.0f);
    out[row * DIM + c] = o;
}

__global__ void copy_kernel(const float* __restrict__ in, float* __restrict__ out, int n) {
    int i = blockIdx.x * blockDim.x + threadIdx.x;
    if (i < n) out[i] = in[i];
}

// ---------------- host ----------------
extern "C" void kernel_launch(void* const* d_in, const int* in_sizes, int n_in,
                              void* d_out, int out_size) {
    const float* x_in   = (const float*)d_in[0];
    const float* abias  = (const float*)d_in[1];
    const float* ln1_g  = (const float*)d_in[2];
    const float* ln1_b  = (const float*)d_in[3];
    const float* Wkv    = (const float*)d_in[4];
    const float* Wq     = (const float*)d_in[5];
    const float* Wo     = (const float*)d_in[6];
    const float* bo     = (const float*)d_in[7];
    const float* ln2_g  = (const float*)d_in[8];
    const float* ln2_b  = (const float*)d_in[9];
    const float* W1     = (const float*)d_in[10];
    const float* b1     = (const float*)d_in[11];
    const float* W2     = (const float*)d_in[12];
    const float* b2     = (const float*)d_in[13];
    const float* Wg     = (const float*)d_in[14];
    const float* lng_g  = (const float*)d_in[15];
    const float* lng_b  = (const float*)d_in[16];
    float* out = (float*)d_out;

    float *px, *pxn, *pxma, *pq, *pkv, *pao, *pG, *pbias, *pdots, *pff;
    cudaGetSymbolAddress((void**)&px, g_x);
    cudaGetSymbolAddress((void**)&pxn, g_xn);
    cudaGetSymbolAddress((void**)&pxma, g_xma);
    cudaGetSymbolAddress((void**)&pq, g_q);
    cudaGetSymbolAddress((void**)&pkv, g_kv);
    cudaGetSymbolAddress((void**)&pao, g_ao);
    cudaGetSymbolAddress((void**)&pG, g_G);
    cudaGetSymbolAddress((void**)&pbias, g_bias);
    cudaGetSymbolAddress((void**)&pdots, g_dots);
    cudaGetSymbolAddress((void**)&pff, g_ff);

    const int ROWS = BB * NN_;           // 4096
    const long ND = (long)NN_ * DIM;
    dim3 blk(256);

    prep_kernel<<<BB * NN_, blk>>>(abias);
    copy_kernel<<<(ROWS * DIM + 255) / 256, blk>>>(x_in, px, ROWS * DIM);

    for (int l = 0; l < DEPTH; l++) {
        // GX = G @ x -> g_xn   [per b: 1024x256, K=1024]
        mma_gemm<64, 64, 32, 16, 0, false><<<dim3(DIM / 64, NN_ / 64, BB), blk>>>(
            pG, px, pxn, nullptr, nullptr,
            NN_, NN_, DIM, DIM,
            (long)NN_ * NN_, 0, ND, 0, ND, 0, 1, 1.0f);
        // x_ma_pre = GX @ Wg -> g_xma   [4096x256, K=256]
        mma_gemm<64, 64, 32, 16, 0, false><<<dim3(DIM / 64, ROWS / 64, 1), blk>>>(
            pxn, Wg, pxma, nullptr, nullptr,
            DIM, DIM, DIM, DIM, 0, 0, 0, 0, 0, 0, 1, 1.0f);
        // x_ma = relu(LN(x_ma_pre)) in place
        ln_kernel<<<ROWS, DIM>>>(pxma, pxma, lng_g, lng_b, 1);
        // xn = LN(x)
        ln_kernel<<<ROWS, DIM>>>(px, pxn, ln1_g + l * DIM, ln1_b + l * DIM, 0);
        // kv = xn @ Wkv[l]   [4096x512, K=256]
        mma_gemm<64, 64, 32, 16, 0, false><<<dim3(2 * DIM / 64, ROWS / 64, 1), blk>>>(
            pxn, Wkv + (long)l * DIM * 2 * DIM, pkv, nullptr, nullptr,
            DIM, DIM, 2 * DIM, 2 * DIM, 0, 0, 0, 0, 0, 0, 1, 1.0f);
        // q = x_ma @ Wq[l]   [4096x256, K=256]
        mma_gemm<64, 64, 32, 16, 0, false><<<dim3(DIM / 64, ROWS / 64, 1), blk>>>(
            pxma, Wq + (long)l * DIM * DIM, pq, nullptr, nullptr,
            DIM, DIM, DIM, DIM, 0, 0, 0, 0, 0, 0, 1, 1.0f);
        // dots = q_h @ k_h^T * scale + add_attn   [per (b,h): 1024x1024, K=64]
        mma_gemm<128, 128, 32, 64, 1, true><<<dim3(NN_ / 128, NN_ / 128, BB * HEADS), blk>>>(
            pq, pkv, pdots, pbias, nullptr,
            DH, DIM, 2 * DIM, NN_,
            ND, DH, (long)NN_ * 2 * DIM, DH,
            (long)HEADS * NN_ * NN_, (long)NN_ * NN_, HEADS, SCALE);
        // softmax rows
        softmax_kernel<<<BB * HEADS * NN_, blk>>>(pdots);
        // out_h = attn @ v_h -> g_ao   [per (b,h): 1024x64, K=1024]
        mma_gemm<64, 64, 32, 16, 0, false><<<dim3(1, NN_ / 64, BB * HEADS), blk>>>(
            pdots, pkv + DIM, pao, nullptr, nullptr,
            NN_, NN_, 2 * DIM, DIM,
            (long)HEADS * NN_ * NN_, (long)NN_ * NN_,
            (long)NN_ * 2 * DIM, DH, ND, DH, HEADS, 1.0f);
        // x = x + out @ Wo[l] + bo[l]
        mma_gemm<64, 64, 32, 16, 2, false><<<dim3(DIM / 64, ROWS / 64, 1), blk>>>(
            pao, Wo + (long)l * DIM * DIM, px, px, bo + l * DIM,
            DIM, DIM, DIM, DIM, 0, 0, 0, 0, 0, 0, 1, 1.0f);
        // xn2 = LN(x)
        ln_kernel<<<ROWS, DIM>>>(px, pxn, ln2_g + l * DIM, ln2_b + l * DIM, 0);
        // ff = gelu(xn2 @ W1[l] + b1[l])   [4096x1024, K=256]
        mma_gemm<128, 128, 32, 64, 3, false><<<dim3(MLP / 128, ROWS / 128, 1), blk>>>(
            pxn, W1 + (long)l * DIM * MLP, pff, nullptr, b1 + l * MLP,
            DIM, DIM, MLP, MLP, 0, 0, 0, 0, 0, 0, 1, 1.0f);
        // x = x + ff @ W2[l] + b2[l]   [4096x256, K=1024]
        mma_gemm<64, 64, 32, 16, 2, false><<<dim3(DIM / 64, ROWS / 64, 1), blk>>>(
            pff, W2 + (long)l * MLP * DIM, px, px, b2 + l * DIM,
            MLP, MLP, DIM, DIM, 0, 0, 0, 0, 0, 0, 1, 1.0f);
    }

    copy_kernel<<<(ROWS * DIM + 255) / 256, blk>>>(px, out, ROWS * DIM);
}

// round 3
// speedup vs baseline: 2.3850x; 1.2556x over previous
#include <cuda_runtime.h>
#include <math.h>
#include <stdint.h>

#define BB 4
#define NN_ 1024
#define DIM 256
#define HEADS 4
#define DH 64
#define DEPTH 4
#define MLP 1024
#define EPS 1e-5f
#define SCALE 0.0625f   // DIM^-0.5

// ---------------- scratch ----------------
__device__ float g_x  [BB*NN_*DIM];
__device__ float g_xn [BB*NN_*DIM];
__device__ float g_xma[BB*NN_*DIM];
__device__ float g_q  [BB*NN_*DIM];
__device__ float g_kv [BB*NN_*2*DIM];
__device__ float g_ao [BB*NN_*DIM];
__device__ float g_G  [(long)BB*NN_*NN_];
__device__ float g_bias[(long)BB*HEADS*NN_*NN_];
__device__ float g_ff [BB*NN_*MLP];

// ---------------- reductions ----------------
__device__ __forceinline__ float warp_sum(float v) {
#pragma unroll
    for (int o = 16; o; o >>= 1) v += __shfl_xor_sync(0xffffffffu, v, o);
    return v;
}
__device__ __forceinline__ float warp_max(float v) {
#pragma unroll
    for (int o = 16; o; o >>= 1) v = fmaxf(v, __shfl_xor_sync(0xffffffffu, v, o));
    return v;
}
__device__ __forceinline__ float block_sum(float v, float* sh) {
    int lane = threadIdx.x & 31, w = threadIdx.x >> 5;
    v = warp_sum(v);
    if (lane == 0) sh[w] = v;
    __syncthreads();
    v = (lane < 8) ? sh[lane] : 0.0f;
    v = warp_sum(v);
    __syncthreads();
    return v;
}
__device__ __forceinline__ float block_max(float v, float* sh) {
    int lane = threadIdx.x & 31, w = threadIdx.x >> 5;
    v = warp_max(v);
    if (lane == 0) sh[w] = v;
    __syncthreads();
    v = (lane < 8) ? sh[lane] : -INFINITY;
    v = warp_max(v);
    __syncthreads();
    return v;
}

// ---------------- tf32 helpers ----------------
__device__ __forceinline__ uint32_t f2tf(float f) {
    uint32_t u;
    asm("cvt.rna.tf32.f32 %0, %1;" : "=r"(u) : "f"(f));
    return u;
}
__device__ __forceinline__ void mma_tf32(float c[4], const uint32_t a[4], const uint32_t b[2]) {
    asm volatile(
        "mma.sync.aligned.m16n8k8.row.col.f32.tf32.tf32.f32 "
        "{%0,%1,%2,%3}, {%4,%5,%6,%7}, {%8,%9}, {%0,%1,%2,%3};"
        : "+f"(c[0]), "+f"(c[1]), "+f"(c[2]), "+f"(c[3])
        : "r"(a[0]), "r"(a[1]), "r"(a[2]), "r"(a[3]), "r"(b[0]), "r"(b[1]));
}
__device__ __forceinline__ uint4 cvt4(float4 v) {
    return make_uint4(f2tf(v.x), f2tf(v.y), f2tf(v.z), f2tf(v.w));
}

// ---------------- dense tf32 GEMM ----------------
// A row-major smem [m][k] (LDA=20: frag LDS fully conflict-free), B [k][n].
// EPI: 0 plain, 2 acc + E[row,col] + bv[col], 3 gelu(acc + bv[col]).
// batch via blockIdx.z with strides Ab/Bb/Cb (E shares Cb).
template <int BM, int BN, int WM, int WN, int EPI>
__global__ __launch_bounds__(256, 2)
void mma_gemm(const float* __restrict__ A, const float* __restrict__ Bm,
              float* __restrict__ C, const float* __restrict__ E,
              const float* __restrict__ bv,
              int K, int lda, int ldb, int ldc,
              long Ab, long Bb, long Cb, float alpha) {
    constexpr int LDA = 20;
    constexpr int LDB = BN + 8;
    constexpr int AF4 = BM / 64;
    constexpr int BF4 = BN / 64;
    constexpr int BNQ = BN / 4;
    constexpr int WARPS_N = BN / WN;
    constexpr int MT = WM / 16, NT = WN / 8;

    __shared__ __align__(16) uint32_t As[2][BM * LDA];
    __shared__ __align__(16) uint32_t Bs[2][16 * LDB];

    int z = blockIdx.z;
    A += (long)z * Ab;
    Bm += (long)z * Bb;
    long co = (long)z * Cb;
    C += co;
    if (EPI == 2) E += co;

    const int tid = threadIdx.x;
    const int wid = tid >> 5, lane = tid & 31;
    const int gid = lane >> 2, tg = lane & 3;
    const int wm0 = (wid / WARPS_N) * WM;
    const int wn0 = (wid % WARPS_N) * WN;
    const int row0 = blockIdx.y * BM, col0 = blockIdx.x * BN;

    float acc[MT][NT][4];
#pragma unroll
    for (int i = 0; i < MT; i++)
#pragma unroll
        for (int j = 0; j < NT; j++)
#pragma unroll
            for (int k = 0; k < 4; k++) acc[i][j][k] = 0.0f;

    float4 ra[AF4], rb[BF4];

    auto ldg_tile = [&](int k0) {
#pragma unroll
        for (int i = 0; i < AF4; i++) {
            int q = tid + i * 256;
            int m = q >> 2, kq = q & 3;
            ra[i] = *(const float4*)(A + (long)(row0 + m) * lda + k0 + 4 * kq);
        }
#pragma unroll
        for (int i = 0; i < BF4; i++) {
            int q = tid + i * 256;
            int kk = q / BNQ, nq = q % BNQ;
            rb[i] = *(const float4*)(Bm + (long)(k0 + kk) * ldb + col0 + 4 * nq);
        }
    };
    auto sts_tile = [&](int buf) {
#pragma unroll
        for (int i = 0; i < AF4; i++) {
            int q = tid + i * 256;
            int m = q >> 2, kq = q & 3;
            *(uint4*)(&As[buf][m * LDA + 4 * kq]) = cvt4(ra[i]);
        }
#pragma unroll
        for (int i = 0; i < BF4; i++) {
            int q = tid + i * 256;
            int kk = q / BNQ, nq = q % BNQ;
            *(uint4*)(&Bs[buf][kk * LDB + 4 * nq]) = cvt4(rb[i]);
        }
    };
    auto compute = [&](int buf) {
#pragma unroll
        for (int ks = 0; ks < 16; ks += 8) {
            uint32_t af[MT][4], bf[NT][2];
#pragma unroll
            for (int mt = 0; mt < MT; mt++) {
                const uint32_t* p = &As[buf][(wm0 + mt * 16 + gid) * LDA + ks + tg];
                af[mt][0] = p[0];
                af[mt][1] = p[8 * LDA];
                af[mt][2] = p[4];
                af[mt][3] = p[8 * LDA + 4];
            }
#pragma unroll
            for (int nt = 0; nt < NT; nt++) {
                const uint32_t* p = &Bs[buf][(ks + tg) * LDB + wn0 + nt * 8 + gid];
                bf[nt][0] = p[0];
                bf[nt][1] = p[4 * LDB];
            }
#pragma unroll
            for (int mt = 0; mt < MT; mt++)
#pragma unroll
                for (int nt = 0; nt < NT; nt++)
                    mma_tf32(acc[mt][nt], af[mt], bf[nt]);
        }
    };

    const int TILES = K / 16;
    ldg_tile(0);
    sts_tile(0);
    __syncthreads();
    for (int t = 0; t < TILES; t++) {
        int cur = t & 1;
        if (t + 1 < TILES) ldg_tile((t + 1) * 16);
        compute(cur);
        if (t + 1 < TILES) sts_tile(cur ^ 1);
        __syncthreads();
    }

#pragma unroll
    for (int mt = 0; mt < MT; mt++)
#pragma unroll
        for (int nt = 0; nt < NT; nt++)
#pragma unroll
            for (int half = 0; half < 2; half++) {
                int r = row0 + wm0 + mt * 16 + gid + half * 8;
                int c = col0 + wn0 + nt * 8 + 2 * tg;
                long off = (long)r * ldc + c;
                float v0 = acc[mt][nt][half * 2 + 0];
                float v1 = acc[mt][nt][half * 2 + 1];
                if (EPI == 2) {
                    float2 e = *(const float2*)(E + off);
                    v0 += e.x + bv[c];
                    v1 += e.y + bv[c + 1];
                } else if (EPI == 3) {
                    v0 += bv[c];
                    v1 += bv[c + 1];
                    v0 = 0.5f * v0 * (1.0f + erff(v0 * 0.70710678118654752f));
                    v1 = 0.5f * v1 * (1.0f + erff(v1 * 0.70710678118654752f));
                }
                float2 o; o.x = v0; o.y = v1;
                *(float2*)(C + off) = o;
            }
}

// ---------------- fused flash attention ----------------
// grid (N/128, HEADS, B); 256 thr = 8 warps, warp owns 16 q-rows (full width).
// S = Q K^T*scale + bias -> online softmax -> O += P V ; O /= l at end.
__global__ __launch_bounds__(256, 1)
void flash_kernel(const float* __restrict__ Qg, const float* __restrict__ KVg,
                  const float* __restrict__ biasg, float* __restrict__ Og) {
    extern __shared__ uint32_t sm[];
    uint32_t* Qs = sm;                  // [128][68]  row-major [qrow][dh]
    uint32_t* Ks = Qs + 128 * 68;       // [128][68]  [key][dh]
    uint32_t* Vs = Ks + 128 * 68;       // [128][72]  [key][dh]

    const int i0 = blockIdx.x * 128;
    const int h = blockIdx.y, b = blockIdx.z;
    const float* Qp = Qg + (long)b * NN_ * DIM + h * DH;
    const float* Kp = KVg + (long)b * NN_ * 2 * DIM + h * DH;
    const float* Vp = Kp + DIM;
    const float* Bp = biasg + ((long)(b * HEADS + h)) * NN_ * NN_ + (long)i0 * NN_;

    const int tid = threadIdx.x, wid = tid >> 5, lane = tid & 31;
    const int gid = lane >> 2, tg = lane & 3;
    const int wm0 = wid * 16;

    // load Q tile (tf32), row-major
#pragma unroll
    for (int t = 0; t < 8; t++) {
        int q = tid + t * 256;
        int m = q >> 4, c4 = (q & 15) << 2;
        float4 v = *(const float4*)(Qp + (long)(i0 + m) * DIM + c4);
        *(uint4*)(Qs + m * 68 + c4) = cvt4(v);
    }

    float oacc[8][4];
#pragma unroll
    for (int i = 0; i < 8; i++)
#pragma unroll
        for (int j = 0; j < 4; j++) oacc[i][j] = 0.0f;
    float mi0 = -1e30f, mi1 = -1e30f, li0 = 0.0f, li1 = 0.0f;

    for (int j0 = 0; j0 < NN_; j0 += 128) {
        __syncthreads();   // previous Vs fully consumed
#pragma unroll
        for (int t = 0; t < 8; t++) {
            int q = tid + t * 256;
            int n = q >> 4, c4 = (q & 15) << 2;
            float4 kv = *(const float4*)(Kp + (long)(j0 + n) * (2 * DIM) + c4);
            *(uint4*)(Ks + n * 68 + c4) = cvt4(kv);
            float4 vv = *(const float4*)(Vp + (long)(j0 + n) * (2 * DIM) + c4);
            *(uint4*)(Vs + n * 72 + c4) = cvt4(vv);
        }
        __syncthreads();

        // S = Q @ K^T  (warp: 16 rows x 128 keys, K=64)
        float s[16][4];
#pragma unroll
        for (int i = 0; i < 16; i++)
#pragma unroll
            for (int j = 0; j < 4; j++) s[i][j] = 0.0f;
#pragma unroll
        for (int ks = 0; ks < 64; ks += 8) {
            uint32_t a[4];
            const uint32_t* pa = Qs + (wm0 + gid) * 68 + ks + tg;
            a[0] = pa[0];
            a[1] = pa[8 * 68];
            a[2] = pa[4];
            a[3] = pa[8 * 68 + 4];
#pragma unroll
            for (int nt = 0; nt < 16; nt++) {
                const uint32_t* pb = Ks + (nt * 8 + gid) * 68 + ks + tg;
                uint32_t bf[2] = { pb[0], pb[4] };
                mma_tf32(s[nt], a, bf);
            }
        }

        // bias + scale, row stats
        float rmax0 = -1e30f, rmax1 = -1e30f;
#pragma unroll
        for (int nt = 0; nt < 16; nt++) {
            long o0 = (long)(wm0 + gid) * NN_ + j0 + nt * 8 + 2 * tg;
            float2 e0 = *(const float2*)(Bp + o0);
            float2 e1 = *(const float2*)(Bp + o0 + 8 * NN_);
            s[nt][0] = fmaf(s[nt][0], SCALE, e0.x);
            s[nt][1] = fmaf(s[nt][1], SCALE, e0.y);
            s[nt][2] = fmaf(s[nt][2], SCALE, e1.x);
            s[nt][3] = fmaf(s[nt][3], SCALE, e1.y);
            rmax0 = fmaxf(rmax0, fmaxf(s[nt][0], s[nt][1]));
            rmax1 = fmaxf(rmax1, fmaxf(s[nt][2], s[nt][3]));
        }
        rmax0 = fmaxf(rmax0, __shfl_xor_sync(0xffffffffu, rmax0, 1));
        rmax0 = fmaxf(rmax0, __shfl_xor_sync(0xffffffffu, rmax0, 2));
        rmax1 = fmaxf(rmax1, __shfl_xor_sync(0xffffffffu, rmax1, 1));
        rmax1 = fmaxf(rmax1, __shfl_xor_sync(0xffffffffu, rmax1, 2));
        float mn0 = fmaxf(mi0, rmax0), mn1 = fmaxf(mi1, rmax1);
        float al0 = __expf(mi0 - mn0), al1 = __expf(mi1 - mn1);
        float rs0 = 0.0f, rs1 = 0.0f;
#pragma unroll
        for (int nt = 0; nt < 16; nt++) {
            s[nt][0] = __expf(s[nt][0] - mn0); rs0 += s[nt][0];
            s[nt][1] = __expf(s[nt][1] - mn0); rs0 += s[nt][1];
            s[nt][2] = __expf(s[nt][2] - mn1); rs1 += s[nt][2];
            s[nt][3] = __expf(s[nt][3] - mn1); rs1 += s[nt][3];
        }
        rs0 += __shfl_xor_sync(0xffffffffu, rs0, 1);
        rs0 += __shfl_xor_sync(0xffffffffu, rs0, 2);
        rs1 += __shfl_xor_sync(0xffffffffu, rs1, 1);
        rs1 += __shfl_xor_sync(0xffffffffu, rs1, 2);
        li0 = li0 * al0 + rs0;
        li1 = li1 * al1 + rs1;
        mi0 = mn0; mi1 = mn1;
#pragma unroll
        for (int nt = 0; nt < 8; nt++) {
            oacc[nt][0] *= al0; oacc[nt][1] *= al0;
            oacc[nt][2] *= al1; oacc[nt][3] *= al1;
        }

        // P frag redistribute (C-layout -> A-layout) via tg-group shuffles, then O += P@V
        const int src = (lane & ~3) | (tg >> 1);
        const bool odd = (tg & 1);
#pragma unroll
        for (int g = 0; g < 16; g++) {
            float f0 = __shfl_sync(0xffffffffu, s[g][0], src);
            float f1 = __shfl_sync(0xffffffffu, s[g][1], src);
            float f2 = __shfl_sync(0xffffffffu, s[g][0], src + 2);
            float f3 = __shfl_sync(0xffffffffu, s[g][1], src + 2);
            float h0 = __shfl_sync(0xffffffffu, s[g][2], src);
            float h1 = __shfl_sync(0xffffffffu, s[g][3], src);
            float h2 = __shfl_sync(0xffffffffu, s[g][2], src + 2);
            float h3 = __shfl_sync(0xffffffffu, s[g][3], src + 2);
            uint32_t pa4[4];
            pa4[0] = f2tf(odd ? f1 : f0);
            pa4[1] = f2tf(odd ? h1 : h0);
            pa4[2] = f2tf(odd ? f3 : f2);
            pa4[3] = f2tf(odd ? h3 : h2);
#pragma unroll
            for (int nt = 0; nt < 8; nt++) {
                const uint32_t* pb = Vs + (g * 8 + tg) * 72 + nt * 8 + gid;
                uint32_t bf[2] = { pb[0], pb[4 * 72] };
                mma_tf32(oacc[nt], pa4, bf);
            }
        }
    }

    // finalize
    float iv0 = 1.0f / li0, iv1 = 1.0f / li1;
#pragma unroll
    for (int nt = 0; nt < 8; nt++) {
        long off = ((long)b * NN_ + i0 + wm0 + gid) * DIM + h * DH + nt * 8 + 2 * tg;
        float2 o0; o0.x = oacc[nt][0] * iv0; o0.y = oacc[nt][1] * iv0;
        float2 o1; o1.x = oacc[nt][2] * iv1; o1.y = oacc[nt][3] * iv1;
        *(float2*)(Og + off) = o0;
        *(float2*)(Og + off + 8 * DIM) = o1;
    }
}

// ---------------- prep: add_attn = b0+b1 ; G = softmax(mean_h(b0)*mean_h(b1)) ----------
__global__ __launch_bounds__(256)
void prep_kernel(const float* __restrict__ ab) {
    __shared__ float sh[32];
    int b = blockIdx.x >> 10;
    int i = blockIdx.x & 1023;
    const long BHNN = (long)BB * HEADS * NN_ * NN_;
    int tid = threadIdx.x;
    float val[4];
#pragma unroll
    for (int t = 0; t < 4; t++) {
        int j = tid + t * 256;
        float sa = 0.0f, sb = 0.0f;
#pragma unroll
        for (int h = 0; h < HEADS; h++) {
            long o = (((long)(b * HEADS + h) * NN_) + i) * NN_ + j;
            float a0 = ab[o];
            float a1 = ab[BHNN + o];
            sa += a0; sb += a1;
            g_bias[o] = a0 + a1;
        }
        val[t] = (sa * 0.25f) * (sb * 0.25f);
    }
    float m = fmaxf(fmaxf(val[0], val[1]), fmaxf(val[2], val[3]));
    m = block_max(m, sh);
    float s = 0.0f;
#pragma unroll
    for (int t = 0; t < 4; t++) { val[t] = __expf(val[t] - m); s += val[t]; }
    s = block_sum(s, sh);
    float inv = 1.0f / s;
    long rowo = ((long)(b * NN_ + i)) * NN_;
#pragma unroll
    for (int t = 0; t < 4; t++) g_G[rowo + tid + t * 256] = val[t] * inv;
}

// ---------------- LayerNorm over DIM=256 ----------------
__global__ __launch_bounds__(256)
void ln_kernel(const float* __restrict__ in, float* __restrict__ out,
               const float* __restrict__ g, const float* __restrict__ bt, int relu) {
    __shared__ float sh[32];
    long row = blockIdx.x;
    int c = threadIdx.x;
    float v = in[row * DIM + c];
    float mean = block_sum(v, sh) * (1.0f / DIM);
    float d = v - mean;
    float var = block_sum(d * d, sh) * (1.0f / DIM);
    float o = d * rsqrtf(var + EPS) * g[c] + bt[c];
    if (relu) o = fmaxf(o, 0.0f);
    out[row * DIM + c] = o;
}

// ---------------- host ----------------
extern "C" void kernel_launch(void* const* d_in, const int* in_sizes, int n_in,
                              void* d_out, int out_size) {
    const float* x_in   = (const float*)d_in[0];
    const float* abias  = (const float*)d_in[1];
    const float* ln1_g  = (const float*)d_in[2];
    const float* ln1_b  = (const float*)d_in[3];
    const float* Wkv    = (const float*)d_in[4];
    const float* Wq     = (const float*)d_in[5];
    const float* Wo     = (const float*)d_in[6];
    const float* bo     = (const float*)d_in[7];
    const float* ln2_g  = (const float*)d_in[8];
    const float* ln2_b  = (const float*)d_in[9];
    const float* W1     = (const float*)d_in[10];
    const float* b1     = (const float*)d_in[11];
    const float* W2     = (const float*)d_in[12];
    const float* b2     = (const float*)d_in[13];
    const float* Wg     = (const float*)d_in[14];
    const float* lng_g  = (const float*)d_in[15];
    const float* lng_b  = (const float*)d_in[16];
    float* out = (float*)d_out;

    float *px, *pxn, *pxma, *pq, *pkv, *pao, *pG, *pbias, *pff;
    cudaGetSymbolAddress((void**)&px, g_x);
    cudaGetSymbolAddress((void**)&pxn, g_xn);
    cudaGetSymbolAddress((void**)&pxma, g_xma);
    cudaGetSymbolAddress((void**)&pq, g_q);
    cudaGetSymbolAddress((void**)&pkv, g_kv);
    cudaGetSymbolAddress((void**)&pao, g_ao);
    cudaGetSymbolAddress((void**)&pG, g_G);
    cudaGetSymbolAddress((void**)&pbias, g_bias);
    cudaGetSymbolAddress((void**)&pff, g_ff);

    const int ROWS = BB * NN_;           // 4096
    const long ND = (long)NN_ * DIM;
    dim3 blk(256);

    const int FLASH_SMEM = (128 * 68 * 2 + 128 * 72) * 4;  // 106496 B
    cudaFuncSetAttribute(flash_kernel, cudaFuncAttributeMaxDynamicSharedMemorySize, FLASH_SMEM);

    prep_kernel<<<BB * NN_, blk>>>(abias);

    for (int l = 0; l < DEPTH; l++) {
        const float* xcur = (l == 0) ? x_in : px;
        // GX = G @ x -> g_xn   [per b: 1024x256, K=1024]
        mma_gemm<128, 64, 32, 32, 0><<<dim3(DIM / 64, NN_ / 128, BB), blk>>>(
            pG, xcur, pxn, nullptr, nullptr,
            NN_, NN_, DIM, DIM,
            (long)NN_ * NN_, ND, ND, 1.0f);
        // x_ma_pre = GX @ Wg -> g_xma   [4096x256, K=256]
        mma_gemm<128, 64, 32, 32, 0><<<dim3(DIM / 64, ROWS / 128, 1), blk>>>(
            pxn, Wg, pxma, nullptr, nullptr,
            DIM, DIM, DIM, DIM, 0, 0, 0, 1.0f);
        // x_ma = relu(LN(x_ma_pre)) in place
        ln_kernel<<<ROWS, DIM>>>(pxma, pxma, lng_g, lng_b, 1);
        // xn = LN(x)
        ln_kernel<<<ROWS, DIM>>>(xcur, pxn, ln1_g + l * DIM, ln1_b + l * DIM, 0);
        // kv = xn @ Wkv[l]   [4096x512, K=256]
        mma_gemm<128, 64, 32, 32, 0><<<dim3(2 * DIM / 64, ROWS / 128, 1), blk>>>(
            pxn, Wkv + (long)l * DIM * 2 * DIM, pkv, nullptr, nullptr,
            DIM, DIM, 2 * DIM, 2 * DIM, 0, 0, 0, 1.0f);
        // q = x_ma @ Wq[l]   [4096x256, K=256]
        mma_gemm<128, 64, 32, 32, 0><<<dim3(DIM / 64, ROWS / 128, 1), blk>>>(
            pxma, Wq + (long)l * DIM * DIM, pq, nullptr, nullptr,
            DIM, DIM, DIM, DIM, 0, 0, 0, 1.0f);
        // fused attention -> g_ao
        flash_kernel<<<dim3(NN_ / 128, HEADS, BB), blk, FLASH_SMEM>>>(pq, pkv, pbias, pao);
        // x = x + out @ Wo[l] + bo[l]
        mma_gemm<128, 64, 32, 32, 2><<<dim3(DIM / 64, ROWS / 128, 1), blk>>>(
            pao, Wo + (long)l * DIM * DIM, px, xcur, bo + l * DIM,
            DIM, DIM, DIM, DIM, 0, 0, 0, 1.0f);
        // xn2 = LN(x)
        ln_kernel<<<ROWS, DIM>>>(px, pxn, ln2_g + l * DIM, ln2_b + l * DIM, 0);
        // ff = gelu(xn2 @ W1[l] + b1[l])   [4096x1024, K=256]
        mma_gemm<128, 128, 64, 32, 3><<<dim3(MLP / 128, ROWS / 128, 1), blk>>>(
            pxn, W1 + (long)l * DIM * MLP, pff, nullptr, b1 + l * MLP,
            DIM, DIM, MLP, MLP, 0, 0, 0, 1.0f);
        // x = x + ff @ W2[l] + b2[l]  (last layer writes d_out directly)
        float* cdst = (l == DEPTH - 1) ? out : px;
        mma_gemm<128, 64, 32, 32, 2><<<dim3(DIM / 64, ROWS / 128, 1), blk>>>(
            pff, W2 + (long)l * MLP * DIM, cdst, px, b2 + l * DIM,
            MLP, MLP, DIM, DIM, 0, 0, 0, 1.0f);
    }
}

// round 4
// speedup vs baseline: 3.0770x; 1.2901x over previous
#include <cuda_runtime.h>
#include <math.h>
#include <stdint.h>

#define BB 4
#define NN_ 1024
#define DIM 256
#define HEADS 4
#define DH 64
#define DEPTH 4
#define MLP 1024
#define EPS 1e-5f
#define SCALE 0.0625f   // DIM^-0.5

// ---------------- scratch ----------------
__device__ float g_x  [BB*NN_*DIM];
__device__ float g_xn [BB*NN_*DIM];
__device__ float g_xma[BB*NN_*DIM];
__device__ float g_q  [BB*NN_*DIM];
__device__ float g_kv [BB*NN_*2*DIM];
__device__ float g_ao [BB*NN_*DIM];
__device__ float g_G  [(long)BB*NN_*NN_];
__device__ float g_bias[(long)BB*HEADS*NN_*NN_];
__device__ float g_ff [BB*NN_*MLP];

// ---------------- helpers ----------------
__device__ __forceinline__ float warp_sum(float v) {
#pragma unroll
    for (int o = 16; o; o >>= 1) v += __shfl_xor_sync(0xffffffffu, v, o);
    return v;
}
__device__ __forceinline__ float warp_max(float v) {
#pragma unroll
    for (int o = 16; o; o >>= 1) v = fmaxf(v, __shfl_xor_sync(0xffffffffu, v, o));
    return v;
}
__device__ __forceinline__ float block_sum(float v, float* sh) {
    int lane = threadIdx.x & 31, w = threadIdx.x >> 5;
    v = warp_sum(v);
    if (lane == 0) sh[w] = v;
    __syncthreads();
    v = (lane < 8) ? sh[lane] : 0.0f;
    v = warp_sum(v);
    __syncthreads();
    return v;
}
__device__ __forceinline__ float block_max(float v, float* sh) {
    int lane = threadIdx.x & 31, w = threadIdx.x >> 5;
    v = warp_max(v);
    if (lane == 0) sh[w] = v;
    __syncthreads();
    v = (lane < 8) ? sh[lane] : -INFINITY;
    v = warp_max(v);
    __syncthreads();
    return v;
}

__device__ __forceinline__ uint32_t f2tf(float f) {
    uint32_t u;
    asm("cvt.rna.tf32.f32 %0, %1;" : "=r"(u) : "f"(f));
    return u;
}
__device__ __forceinline__ uint32_t tfb(uint32_t bits) {   // raw fp32 bits -> tf32 (RNA)
    return f2tf(__uint_as_float(bits));
}
__device__ __forceinline__ void mma_tf32(float c[4], const uint32_t a[4], const uint32_t b[2]) {
    asm volatile(
        "mma.sync.aligned.m16n8k8.row.col.f32.tf32.tf32.f32 "
        "{%0,%1,%2,%3}, {%4,%5,%6,%7}, {%8,%9}, {%0,%1,%2,%3};"
        : "+f"(c[0]), "+f"(c[1]), "+f"(c[2]), "+f"(c[3])
        : "r"(a[0]), "r"(a[1]), "r"(a[2]), "r"(a[3]), "r"(b[0]), "r"(b[1]));
}
__device__ __forceinline__ uint4 cvt4(float4 v) {
    return make_uint4(f2tf(v.x), f2tf(v.y), f2tf(v.z), f2tf(v.w));
}
__device__ __forceinline__ uint32_t smem_u32(const void* p) {
    return (uint32_t)__cvta_generic_to_shared(p);
}
__device__ __forceinline__ void cpa16(uint32_t dst, const void* src) {
    asm volatile("cp.async.cg.shared.global [%0], [%1], 16;" :: "r"(dst), "l"(src));
}
__device__ __forceinline__ void cp_commit() { asm volatile("cp.async.commit_group;"); }
template <int N> __device__ __forceinline__ void cp_wait() {
    asm volatile("cp.async.wait_group %0;" :: "n"(N));
}

// ---------------- dense tf32 GEMM, cp.async 3-stage, BK=32 ----------------
// smem holds raw fp32; RNA tf32 conversion at LDS time.
// EPI: 0 plain, 2 acc + E[row,col] + bv[col], 3 gelu(acc + bv[col]).
template <int BM, int BN, int WM, int WN, int EPI>
__global__ __launch_bounds__(256)
void mma_gemm(const float* __restrict__ A, const float* __restrict__ Bm,
              float* __restrict__ C, const float* __restrict__ E,
              const float* __restrict__ bv,
              int K, int lda, int ldb, int ldc,
              long Ab, long Bb, long Cb) {
    constexpr int BK = 32;
    constexpr int LDA = 36;               // 36 % 32 == 4 -> frag LDS conflict-free
    constexpr int LDB = BN + 8;
    constexpr int STAGES = 3;
    constexpr int AW = BM * BK / 4 / 256; // cp.async per thread (A)
    constexpr int BW = BK * BN / 4 / 256;
    constexpr int BNQ = BN / 4;
    constexpr int WARPS_N = BN / WN;
    constexpr int MT = WM / 16, NT = WN / 8;

    extern __shared__ __align__(16) uint32_t smraw[];
    uint32_t* As = smraw;                         // [STAGES][BM*LDA]
    uint32_t* Bs = smraw + STAGES * BM * LDA;     // [STAGES][BK*LDB]

    int z = blockIdx.z;
    A += (long)z * Ab;
    Bm += (long)z * Bb;
    long co = (long)z * Cb;
    C += co;
    if (EPI == 2) E += co;

    const int tid = threadIdx.x, wid = tid >> 5, lane = tid & 31;
    const int gid = lane >> 2, tg = lane & 3;
    const int wm0 = (wid / WARPS_N) * WM, wn0 = (wid % WARPS_N) * WN;
    const int row0 = blockIdx.y * BM, col0 = blockIdx.x * BN;

    float acc[MT][NT][4];
#pragma unroll
    for (int i = 0; i < MT; i++)
#pragma unroll
        for (int j = 0; j < NT; j++)
#pragma unroll
            for (int k = 0; k < 4; k++) acc[i][j][k] = 0.0f;

    auto issue = [&](int buf, int t) {
        int k0 = t * BK;
        uint32_t as = smem_u32(As + buf * BM * LDA);
        uint32_t bs = smem_u32(Bs + buf * BK * LDB);
#pragma unroll
        for (int i = 0; i < AW; i++) {
            int q = tid + i * 256;
            int m = q >> 3, kq = q & 7;
            cpa16(as + (m * LDA + 4 * kq) * 4,
                  A + (long)(row0 + m) * lda + k0 + 4 * kq);
        }
#pragma unroll
        for (int i = 0; i < BW; i++) {
            int q = tid + i * 256;
            int kk = q / BNQ, nq = q % BNQ;
            cpa16(bs + (kk * LDB + 4 * nq) * 4,
                  Bm + (long)(k0 + kk) * ldb + col0 + 4 * nq);
        }
        cp_commit();
    };
    auto compute = [&](int buf) {
        const uint32_t* ab = As + buf * BM * LDA;
        const uint32_t* bb = Bs + buf * BK * LDB;
#pragma unroll
        for (int ks = 0; ks < BK; ks += 8) {
            uint32_t af[MT][4], bf[NT][2];
#pragma unroll
            for (int mt = 0; mt < MT; mt++) {
                const uint32_t* p = ab + (wm0 + mt * 16 + gid) * LDA + ks + tg;
                af[mt][0] = tfb(p[0]);
                af[mt][1] = tfb(p[8 * LDA]);
                af[mt][2] = tfb(p[4]);
                af[mt][3] = tfb(p[8 * LDA + 4]);
            }
#pragma unroll
            for (int nt = 0; nt < NT; nt++) {
                const uint32_t* p = bb + (ks + tg) * LDB + wn0 + nt * 8 + gid;
                bf[nt][0] = tfb(p[0]);
                bf[nt][1] = tfb(p[4 * LDB]);
            }
#pragma unroll
            for (int mt = 0; mt < MT; mt++)
#pragma unroll
                for (int nt = 0; nt < NT; nt++)
                    mma_tf32(acc[mt][nt], af[mt], bf[nt]);
        }
    };

    const int TILES = K / BK;
#pragma unroll
    for (int t = 0; t < STAGES - 1; t++) issue(t, t);
    for (int t = 0; t < TILES; t++) {
        cp_wait<STAGES - 2>();
        __syncthreads();
        if (t + STAGES - 1 < TILES) issue((t + STAGES - 1) % STAGES, t + STAGES - 1);
        else cp_commit();                 // keep group arithmetic consistent
        compute(t % STAGES);
    }

#pragma unroll
    for (int mt = 0; mt < MT; mt++)
#pragma unroll
        for (int nt = 0; nt < NT; nt++)
#pragma unroll
            for (int half = 0; half < 2; half++) {
                int r = row0 + wm0 + mt * 16 + gid + half * 8;
                int c = col0 + wn0 + nt * 8 + 2 * tg;
                long off = (long)r * ldc + c;
                float v0 = acc[mt][nt][half * 2 + 0];
                float v1 = acc[mt][nt][half * 2 + 1];
                if (EPI == 2) {
                    float2 e = *(const float2*)(E + off);
                    v0 += e.x + bv[c];
                    v1 += e.y + bv[c + 1];
                } else if (EPI == 3) {
                    v0 += bv[c];
                    v1 += bv[c + 1];
                    v0 = 0.5f * v0 * (1.0f + erff(v0 * 0.70710678118654752f));
                    v1 = 0.5f * v1 * (1.0f + erff(v1 * 0.70710678118654752f));
                }
                float2 o; o.x = v0; o.y = v1;
                *(float2*)(C + off) = o;
            }
}

// ---------------- fused flash attention, cp.async double-buffered K/V ----------------
__global__ __launch_bounds__(256)
void flash_kernel(const float* __restrict__ Qg, const float* __restrict__ KVg,
                  const float* __restrict__ biasg, float* __restrict__ Og) {
    extern __shared__ uint32_t sm[];
    uint32_t* Qs = sm;                    // [128][68] tf32 (pre-converted)
    uint32_t* Ks = Qs + 128 * 68;         // [2][128*68] raw fp32
    uint32_t* Vs = Ks + 2 * 128 * 68;     // [2][128*72] raw fp32

    const int i0 = blockIdx.x * 128;
    const int h = blockIdx.y, b = blockIdx.z;
    const float* Qp = Qg + (long)b * NN_ * DIM + h * DH;
    const float* Kp = KVg + (long)b * NN_ * 2 * DIM + h * DH;
    const float* Vp = Kp + DIM;
    const float* Bp = biasg + ((long)(b * HEADS + h)) * NN_ * NN_ + (long)i0 * NN_;

    const int tid = threadIdx.x, wid = tid >> 5, lane = tid & 31;
    const int gid = lane >> 2, tg = lane & 3;
    const int wm0 = wid * 16;

    auto issue_kv = [&](int buf, int j0) {
        uint32_t ks = smem_u32(Ks + buf * 128 * 68);
        uint32_t vs = smem_u32(Vs + buf * 128 * 72);
#pragma unroll
        for (int t = 0; t < 8; t++) {
            int q = tid + t * 256;
            int n = q >> 4, c4 = (q & 15) << 2;
            cpa16(ks + (n * 68 + c4) * 4, Kp + (long)(j0 + n) * (2 * DIM) + c4);
            cpa16(vs + (n * 72 + c4) * 4, Vp + (long)(j0 + n) * (2 * DIM) + c4);
        }
        cp_commit();
    };

    issue_kv(0, 0);

    // Q tile (tf32, converted once)
#pragma unroll
    for (int t = 0; t < 8; t++) {
        int q = tid + t * 256;
        int m = q >> 4, c4 = (q & 15) << 2;
        float4 v = *(const float4*)(Qp + (long)(i0 + m) * DIM + c4);
        *(uint4*)(Qs + m * 68 + c4) = cvt4(v);
    }

    float oacc[8][4];
#pragma unroll
    for (int i = 0; i < 8; i++)
#pragma unroll
        for (int j = 0; j < 4; j++) oacc[i][j] = 0.0f;
    float mi0 = -1e30f, mi1 = -1e30f, li0 = 0.0f, li1 = 0.0f;

    for (int t = 0; t < NN_ / 128; t++) {
        const int j0 = t * 128;
        const int buf = t & 1;
        cp_wait<0>();
        __syncthreads();
        if (t + 1 < NN_ / 128) issue_kv(buf ^ 1, j0 + 128);

        const uint32_t* kb = Ks + buf * 128 * 68;
        const uint32_t* vb = Vs + buf * 128 * 72;

        // S = Q @ K^T
        float s[16][4];
#pragma unroll
        for (int i = 0; i < 16; i++)
#pragma unroll
            for (int j = 0; j < 4; j++) s[i][j] = 0.0f;
#pragma unroll
        for (int ks = 0; ks < 64; ks += 8) {
            uint32_t a[4];
            const uint32_t* pa = Qs + (wm0 + gid) * 68 + ks + tg;
            a[0] = pa[0];
            a[1] = pa[8 * 68];
            a[2] = pa[4];
            a[3] = pa[8 * 68 + 4];
#pragma unroll
            for (int nt = 0; nt < 16; nt++) {
                const uint32_t* pb = kb + (nt * 8 + gid) * 68 + ks + tg;
                uint32_t bf[2] = { tfb(pb[0]), tfb(pb[4]) };
                mma_tf32(s[nt], a, bf);
            }
        }

        // bias + scale, row stats
        float rmax0 = -1e30f, rmax1 = -1e30f;
#pragma unroll
        for (int nt = 0; nt < 16; nt++) {
            long o0 = (long)(wm0 + gid) * NN_ + j0 + nt * 8 + 2 * tg;
            float2 e0 = *(const float2*)(Bp + o0);
            float2 e1 = *(const float2*)(Bp + o0 + 8 * NN_);
            s[nt][0] = fmaf(s[nt][0], SCALE, e0.x);
            s[nt][1] = fmaf(s[nt][1], SCALE, e0.y);
            s[nt][2] = fmaf(s[nt][2], SCALE, e1.x);
            s[nt][3] = fmaf(s[nt][3], SCALE, e1.y);
            rmax0 = fmaxf(rmax0, fmaxf(s[nt][0], s[nt][1]));
            rmax1 = fmaxf(rmax1, fmaxf(s[nt][2], s[nt][3]));
        }
        rmax0 = fmaxf(rmax0, __shfl_xor_sync(0xffffffffu, rmax0, 1));
        rmax0 = fmaxf(rmax0, __shfl_xor_sync(0xffffffffu, rmax0, 2));
        rmax1 = fmaxf(rmax1, __shfl_xor_sync(0xffffffffu, rmax1, 1));
        rmax1 = fmaxf(rmax1, __shfl_xor_sync(0xffffffffu, rmax1, 2));
        float mn0 = fmaxf(mi0, rmax0), mn1 = fmaxf(mi1, rmax1);
        float al0 = __expf(mi0 - mn0), al1 = __expf(mi1 - mn1);
        float rs0 = 0.0f, rs1 = 0.0f;
#pragma unroll
        for (int nt = 0; nt < 16; nt++) {
            s[nt][0] = __expf(s[nt][0] - mn0); rs0 += s[nt][0];
            s[nt][1] = __expf(s[nt][1] - mn0); rs0 += s[nt][1];
            s[nt][2] = __expf(s[nt][2] - mn1); rs1 += s[nt][2];
            s[nt][3] = __expf(s[nt][3] - mn1); rs1 += s[nt][3];
        }
        rs0 += __shfl_xor_sync(0xffffffffu, rs0, 1);
        rs0 += __shfl_xor_sync(0xffffffffu, rs0, 2);
        rs1 += __shfl_xor_sync(0xffffffffu, rs1, 1);
        rs1 += __shfl_xor_sync(0xffffffffu, rs1, 2);
        li0 = li0 * al0 + rs0;
        li1 = li1 * al1 + rs1;
        mi0 = mn0; mi1 = mn1;
#pragma unroll
        for (int nt = 0; nt < 8; nt++) {
            oacc[nt][0] *= al0; oacc[nt][1] *= al0;
            oacc[nt][2] *= al1; oacc[nt][3] *= al1;
        }

        // P redistribute (C-frag -> A-frag) via shuffles, then O += P @ V
        const int src = (lane & ~3) | (tg >> 1);
        const bool odd = (tg & 1);
#pragma unroll
        for (int g = 0; g < 16; g++) {
            float f0 = __shfl_sync(0xffffffffu, s[g][0], src);
            float f1 = __shfl_sync(0xffffffffu, s[g][1], src);
            float f2 = __shfl_sync(0xffffffffu, s[g][0], src + 2);
            float f3 = __shfl_sync(0xffffffffu, s[g][1], src + 2);
            float h0 = __shfl_sync(0xffffffffu, s[g][2], src);
            float h1 = __shfl_sync(0xffffffffu, s[g][3], src);
            float h2 = __shfl_sync(0xffffffffu, s[g][2], src + 2);
            float h3 = __shfl_sync(0xffffffffu, s[g][3], src + 2);
            uint32_t pa4[4];
            pa4[0] = f2tf(odd ? f1 : f0);
            pa4[1] = f2tf(odd ? h1 : h0);
            pa4[2] = f2tf(odd ? f3 : f2);
            pa4[3] = f2tf(odd ? h3 : h2);
#pragma unroll
            for (int nt = 0; nt < 8; nt++) {
                const uint32_t* pb = vb + (g * 8 + tg) * 72 + nt * 8 + gid;
                uint32_t bf[2] = { tfb(pb[0]), tfb(pb[4 * 72]) };
                mma_tf32(oacc[nt], pa4, bf);
            }
        }
    }

    float iv0 = 1.0f / li0, iv1 = 1.0f / li1;
#pragma unroll
    for (int nt = 0; nt < 8; nt++) {
        long off = ((long)b * NN_ + i0 + wm0 + gid) * DIM + h * DH + nt * 8 + 2 * tg;
        float2 o0; o0.x = oacc[nt][0] * iv0; o0.y = oacc[nt][1] * iv0;
        float2 o1; o1.x = oacc[nt][2] * iv1; o1.y = oacc[nt][3] * iv1;
        *(float2*)(Og + off) = o0;
        *(float2*)(Og + off + 8 * DIM) = o1;
    }
}

// ---------------- prep (float4): add_attn = b0+b1 ; G = softmax(mean(b0)*mean(b1)) ----------
__global__ __launch_bounds__(256)
void prep_kernel(const float* __restrict__ ab) {
    __shared__ float sh[32];
    int b = blockIdx.x >> 10;
    int i = blockIdx.x & 1023;
    const long BHNN = (long)BB * HEADS * NN_ * NN_;
    int tid = threadIdx.x;
    int j4 = tid * 4;
    float4 sa = make_float4(0, 0, 0, 0), sb = make_float4(0, 0, 0, 0);
#pragma unroll
    for (int h = 0; h < HEADS; h++) {
        long o = (((long)(b * HEADS + h) * NN_) + i) * NN_ + j4;
        float4 a0 = *(const float4*)(ab + o);
        float4 a1 = *(const float4*)(ab + BHNN + o);
        sa.x += a0.x; sa.y += a0.y; sa.z += a0.z; sa.w += a0.w;
        sb.x += a1.x; sb.y += a1.y; sb.z += a1.z; sb.w += a1.w;
        float4 sum; sum.x = a0.x + a1.x; sum.y = a0.y + a1.y;
        sum.z = a0.z + a1.z; sum.w = a0.w + a1.w;
        *(float4*)(g_bias + o) = sum;
    }
    float val[4];
    val[0] = (sa.x * 0.25f) * (sb.x * 0.25f);
    val[1] = (sa.y * 0.25f) * (sb.y * 0.25f);
    val[2] = (sa.z * 0.25f) * (sb.z * 0.25f);
    val[3] = (sa.w * 0.25f) * (sb.w * 0.25f);
    float m = fmaxf(fmaxf(val[0], val[1]), fmaxf(val[2], val[3]));
    m = block_max(m, sh);
    float s = 0.0f;
#pragma unroll
    for (int t = 0; t < 4; t++) { val[t] = __expf(val[t] - m); s += val[t]; }
    s = block_sum(s, sh);
    float inv = 1.0f / s;
    long rowo = ((long)(b * NN_ + i)) * NN_ + j4;
    float4 g4; g4.x = val[0] * inv; g4.y = val[1] * inv; g4.z = val[2] * inv; g4.w = val[3] * inv;
    *(float4*)(g_G + rowo) = g4;
}

// ---------------- LayerNorm: one warp per row, float4, shuffle-only ----------------
__global__ __launch_bounds__(256)
void ln_kernel(const float* __restrict__ in, float* __restrict__ out,
               const float* __restrict__ g, const float* __restrict__ bt, int relu) {
    int w = threadIdx.x >> 5, lane = threadIdx.x & 31;
    long row = (long)blockIdx.x * 8 + w;
    const float* p = in + row * DIM + lane * 8;
    float4 v0 = *(const float4*)p;
    float4 v1 = *(const float4*)(p + 4);
    float s = v0.x + v0.y + v0.z + v0.w + v1.x + v1.y + v1.z + v1.w;
    float mean = warp_sum(s) * (1.0f / DIM);
    float d[8] = { v0.x - mean, v0.y - mean, v0.z - mean, v0.w - mean,
                   v1.x - mean, v1.y - mean, v1.z - mean, v1.w - mean };
    float q = 0.0f;
#pragma unroll
    for (int t = 0; t < 8; t++) q += d[t] * d[t];
    float rstd = rsqrtf(warp_sum(q) * (1.0f / DIM) + EPS);
    const float* gp = g + lane * 8;
    const float* bp = bt + lane * 8;
    float4 g0 = *(const float4*)gp, g1 = *(const float4*)(gp + 4);
    float4 b0 = *(const float4*)bp, b1 = *(const float4*)(bp + 4);
    float o[8];
    o[0] = d[0] * rstd * g0.x + b0.x; o[1] = d[1] * rstd * g0.y + b0.y;
    o[2] = d[2] * rstd * g0.z + b0.z; o[3] = d[3] * rstd * g0.w + b0.w;
    o[4] = d[4] * rstd * g1.x + b1.x; o[5] = d[5] * rstd * g1.y + b1.y;
    o[6] = d[6] * rstd * g1.z + b1.z; o[7] = d[7] * rstd * g1.w + b1.w;
    if (relu) {
#pragma unroll
        for (int t = 0; t < 8; t++) o[t] = fmaxf(o[t], 0.0f);
    }
    float* po = out + row * DIM + lane * 8;
    float4 r0; r0.x = o[0]; r0.y = o[1]; r0.z = o[2]; r0.w = o[3];
    float4 r1; r1.x = o[4]; r1.y = o[5]; r1.z = o[6]; r1.w = o[7];
    *(float4*)po = r0;
    *(float4*)(po + 4) = r1;
}

// ---------------- host ----------------
extern "C" void kernel_launch(void* const* d_in, const int* in_sizes, int n_in,
                              void* d_out, int out_size) {
    const float* x_in   = (const float*)d_in[0];
    const float* abias  = (const float*)d_in[1];
    const float* ln1_g  = (const float*)d_in[2];
    const float* ln1_b  = (const float*)d_in[3];
    const float* Wkv    = (const float*)d_in[4];
    const float* Wq     = (const float*)d_in[5];
    const float* Wo     = (const float*)d_in[6];
    const float* bo     = (const float*)d_in[7];
    const float* ln2_g  = (const float*)d_in[8];
    const float* ln2_b  = (const float*)d_in[9];
    const float* W1     = (const float*)d_in[10];
    const float* b1     = (const float*)d_in[11];
    const float* W2     = (const float*)d_in[12];
    const float* b2     = (const float*)d_in[13];
    const float* Wg     = (const float*)d_in[14];
    const float* lng_g  = (const float*)d_in[15];
    const float* lng_b  = (const float*)d_in[16];
    float* out = (float*)d_out;

    float *px, *pxn, *pxma, *pq, *pkv, *pao, *pG, *pbias, *pff;
    cudaGetSymbolAddress((void**)&px, g_x);
    cudaGetSymbolAddress((void**)&pxn, g_xn);
    cudaGetSymbolAddress((void**)&pxma, g_xma);
    cudaGetSymbolAddress((void**)&pq, g_q);
    cudaGetSymbolAddress((void**)&pkv, g_kv);
    cudaGetSymbolAddress((void**)&pao, g_ao);
    cudaGetSymbolAddress((void**)&pG, g_G);
    cudaGetSymbolAddress((void**)&pbias, g_bias);
    cudaGetSymbolAddress((void**)&pff, g_ff);

    const int ROWS = BB * NN_;           // 4096
    const long ND = (long)NN_ * DIM;
    dim3 blk(256);

    // dynamic smem sizes
    const int SM_G64  = 3 * (128 * 36 + 32 * 72) * 4;    // 82944
    const int SM_G128 = 3 * (128 * 36 + 32 * 136) * 4;   // 107520
    const int SM_FL   = (128 * 68 + 2 * 128 * 68 + 2 * 128 * 72) * 4;  // 178176
    cudaFuncSetAttribute(mma_gemm<128, 64, 32, 32, 0>, cudaFuncAttributeMaxDynamicSharedMemorySize, SM_G64);
    cudaFuncSetAttribute(mma_gemm<128, 64, 32, 32, 2>, cudaFuncAttributeMaxDynamicSharedMemorySize, SM_G64);
    cudaFuncSetAttribute(mma_gemm<128, 128, 64, 32, 3>, cudaFuncAttributeMaxDynamicSharedMemorySize, SM_G128);
    cudaFuncSetAttribute(flash_kernel, cudaFuncAttributeMaxDynamicSharedMemorySize, SM_FL);

    prep_kernel<<<BB * NN_, blk>>>(abias);

    for (int l = 0; l < DEPTH; l++) {
        const float* xcur = (l == 0) ? x_in : px;
        // GX = G @ x -> g_xn   [per b: 1024x256, K=1024]
        mma_gemm<128, 64, 32, 32, 0><<<dim3(DIM / 64, NN_ / 128, BB), blk, SM_G64>>>(
            pG, xcur, pxn, nullptr, nullptr,
            NN_, NN_, DIM, DIM, (long)NN_ * NN_, ND, ND);
        // x_ma_pre = GX @ Wg -> g_xma   [4096x256, K=256]
        mma_gemm<128, 64, 32, 32, 0><<<dim3(DIM / 64, ROWS / 128, 1), blk, SM_G64>>>(
            pxn, Wg, pxma, nullptr, nullptr,
            DIM, DIM, DIM, DIM, 0, 0, 0);
        // x_ma = relu(LN(x_ma_pre)) in place
        ln_kernel<<<ROWS / 8, blk>>>(pxma, pxma, lng_g, lng_b, 1);
        // xn = LN(x)
        ln_kernel<<<ROWS / 8, blk>>>(xcur, pxn, ln1_g + l * DIM, ln1_b + l * DIM, 0);
        // kv = xn @ Wkv[l]   [4096x512, K=256]
        mma_gemm<128, 64, 32, 32, 0><<<dim3(2 * DIM / 64, ROWS / 128, 1), blk, SM_G64>>>(
            pxn, Wkv + (long)l * DIM * 2 * DIM, pkv, nullptr, nullptr,
            DIM, DIM, 2 * DIM, 2 * DIM, 0, 0, 0);
        // q = x_ma @ Wq[l]   [4096x256, K=256]
        mma_gemm<128, 64, 32, 32, 0><<<dim3(DIM / 64, ROWS / 128, 1), blk, SM_G64>>>(
            pxma, Wq + (long)l * DIM * DIM, pq, nullptr, nullptr,
            DIM, DIM, DIM, DIM, 0, 0, 0);
        // fused attention -> g_ao
        flash_kernel<<<dim3(NN_ / 128, HEADS, BB), blk, SM_FL>>>(pq, pkv, pbias, pao);
        // x = x + out @ Wo[l] + bo[l]
        mma_gemm<128, 64, 32, 32, 2><<<dim3(DIM / 64, ROWS / 128, 1), blk, SM_G64>>>(
            pao, Wo + (long)l * DIM * DIM, px, xcur, bo + l * DIM,
            DIM, DIM, DIM, DIM, 0, 0, 0);
        // xn2 = LN(x)
        ln_kernel<<<ROWS / 8, blk>>>(px, pxn, ln2_g + l * DIM, ln2_b + l * DIM, 0);
        // ff = gelu(xn2 @ W1[l] + b1[l])   [4096x1024, K=256]
        mma_gemm<128, 128, 64, 32, 3><<<dim3(MLP / 128, ROWS / 128, 1), blk, SM_G128>>>(
            pxn, W1 + (long)l * DIM * MLP, pff, nullptr, b1 + l * MLP,
            DIM, DIM, MLP, MLP, 0, 0, 0);
        // x = x + ff @ W2[l] + b2[l]  (last layer writes d_out directly)
        float* cdst = (l == DEPTH - 1) ? out : px;
        mma_gemm<128, 64, 32, 32, 2><<<dim3(DIM / 64, ROWS / 128, 1), blk, SM_G64>>>(
            pff, W2 + (long)l * MLP * DIM, cdst, px, b2 + l * DIM,
            MLP, MLP, DIM, DIM, 0, 0, 0);
    }
}

// round 5
// speedup vs baseline: 3.1040x; 1.0088x over previous
#include <cuda_runtime.h>
#include <cuda_fp16.h>
#include <math.h>
#include <stdint.h>

#define BB 4
#define NN_ 1024
#define DIM 256
#define HEADS 4
#define DH 64
#define DEPTH 4
#define MLP 1024
#define EPS 1e-5f
#define SCALE 0.0625f   // DIM^-0.5

// ---------------- scratch ----------------
__device__ float g_x  [BB*NN_*DIM];
__device__ float g_xn [BB*NN_*DIM];
__device__ float g_xma[BB*NN_*DIM];
__device__ float g_q  [BB*NN_*DIM];
__device__ float g_kv [BB*NN_*2*DIM];
__device__ float g_ao [BB*NN_*DIM];
__device__ float g_G  [(long)BB*NN_*NN_];
__device__ __half g_bias[(long)BB*HEADS*NN_*NN_];   // fp16: halves flash bias traffic
__device__ float g_ff [BB*NN_*MLP];

// ---------------- helpers ----------------
__device__ __forceinline__ float warp_sum(float v) {
#pragma unroll
    for (int o = 16; o; o >>= 1) v += __shfl_xor_sync(0xffffffffu, v, o);
    return v;
}
__device__ __forceinline__ float warp_max(float v) {
#pragma unroll
    for (int o = 16; o; o >>= 1) v = fmaxf(v, __shfl_xor_sync(0xffffffffu, v, o));
    return v;
}
__device__ __forceinline__ float block_sum(float v, float* sh) {
    int lane = threadIdx.x & 31, w = threadIdx.x >> 5;
    v = warp_sum(v);
    if (lane == 0) sh[w] = v;
    __syncthreads();
    v = (lane < 8) ? sh[lane] : 0.0f;
    v = warp_sum(v);
    __syncthreads();
    return v;
}
__device__ __forceinline__ float block_max(float v, float* sh) {
    int lane = threadIdx.x & 31, w = threadIdx.x >> 5;
    v = warp_max(v);
    if (lane == 0) sh[w] = v;
    __syncthreads();
    v = (lane < 8) ? sh[lane] : -INFINITY;
    v = warp_max(v);
    __syncthreads();
    return v;
}

__device__ __forceinline__ uint32_t f2tf(float f) {
    uint32_t u;
    asm("cvt.rna.tf32.f32 %0, %1;" : "=r"(u) : "f"(f));
    return u;
}
__device__ __forceinline__ uint32_t tfb(uint32_t bits) {
    return f2tf(__uint_as_float(bits));
}
__device__ __forceinline__ void mma_tf32(float c[4], const uint32_t a[4], const uint32_t b[2]) {
    asm volatile(
        "mma.sync.aligned.m16n8k8.row.col.f32.tf32.tf32.f32 "
        "{%0,%1,%2,%3}, {%4,%5,%6,%7}, {%8,%9}, {%0,%1,%2,%3};"
        : "+f"(c[0]), "+f"(c[1]), "+f"(c[2]), "+f"(c[3])
        : "r"(a[0]), "r"(a[1]), "r"(a[2]), "r"(a[3]), "r"(b[0]), "r"(b[1]));
}
__device__ __forceinline__ uint4 cvt4(float4 v) {
    return make_uint4(f2tf(v.x), f2tf(v.y), f2tf(v.z), f2tf(v.w));
}
__device__ __forceinline__ uint32_t smem_u32(const void* p) {
    return (uint32_t)__cvta_generic_to_shared(p);
}
__device__ __forceinline__ void cpa16(uint32_t dst, const void* src) {
    asm volatile("cp.async.cg.shared.global [%0], [%1], 16;" :: "r"(dst), "l"(src));
}
__device__ __forceinline__ void cp_commit() { asm volatile("cp.async.commit_group;"); }
template <int N> __device__ __forceinline__ void cp_wait() {
    asm volatile("cp.async.wait_group %0;" :: "n"(N));
}

// ---------------- dense GEMM core: BM=128 BN=64 WM=32 WN=32 BK=32, 2-stage ----------------
// smem: As[2][128*36] + Bs[2][32*72] = 55296 B (fits 2 CTAs/SM)
#define LDA 36
#define LDB 72
#define SM_WORDS (2 * 128 * LDA + 2 * 32 * LDB)

template <int EPI>
__device__ __forceinline__ void gemm_core(
    const float* __restrict__ A, const float* __restrict__ Bm,
    float* __restrict__ C, const float* __restrict__ E, const float* __restrict__ bv,
    int K, int lda, int ldb, int ldc, int row0, int col0, uint32_t* smraw) {
    uint32_t* As = smraw;
    uint32_t* Bs = smraw + 2 * 128 * LDA;

    const int tid = threadIdx.x, wid = tid >> 5, lane = tid & 31;
    const int gid = lane >> 2, tg = lane & 3;
    const int wm0 = (wid >> 1) * 32, wn0 = (wid & 1) * 32;

    float acc[2][4][4];
#pragma unroll
    for (int i = 0; i < 2; i++)
#pragma unroll
        for (int j = 0; j < 4; j++)
#pragma unroll
            for (int k = 0; k < 4; k++) acc[i][j][k] = 0.0f;

    auto issue = [&](int buf, int t) {
        int k0 = t * 32;
        uint32_t as = smem_u32(As + buf * 128 * LDA);
        uint32_t bs = smem_u32(Bs + buf * 32 * LDB);
#pragma unroll
        for (int i = 0; i < 4; i++) {           // A: 128*32/4/256 = 4
            int q = tid + i * 256;
            int m = q >> 3, kq = q & 7;
            cpa16(as + (m * LDA + 4 * kq) * 4,
                  A + (long)(row0 + m) * lda + k0 + 4 * kq);
        }
#pragma unroll
        for (int i = 0; i < 2; i++) {           // B: 32*64/4/256 = 2
            int q = tid + i * 256;
            int kk = q >> 4, nq = q & 15;
            cpa16(bs + (kk * LDB + 4 * nq) * 4,
                  Bm + (long)(k0 + kk) * ldb + col0 + 4 * nq);
        }
        cp_commit();
    };
    auto compute = [&](int buf) {
        const uint32_t* ab = As + buf * 128 * LDA;
        const uint32_t* bb = Bs + buf * 32 * LDB;
#pragma unroll
        for (int ks = 0; ks < 32; ks += 8) {
            uint32_t af[2][4], bf[4][2];
#pragma unroll
            for (int mt = 0; mt < 2; mt++) {
                const uint32_t* p = ab + (wm0 + mt * 16 + gid) * LDA + ks + tg;
                af[mt][0] = tfb(p[0]);
                af[mt][1] = tfb(p[8 * LDA]);
                af[mt][2] = tfb(p[4]);
                af[mt][3] = tfb(p[8 * LDA + 4]);
            }
#pragma unroll
            for (int nt = 0; nt < 4; nt++) {
                const uint32_t* p = bb + (ks + tg) * LDB + wn0 + nt * 8 + gid;
                bf[nt][0] = tfb(p[0]);
                bf[nt][1] = tfb(p[4 * LDB]);
            }
#pragma unroll
            for (int mt = 0; mt < 2; mt++)
#pragma unroll
                for (int nt = 0; nt < 4; nt++)
                    mma_tf32(acc[mt][nt], af[mt], bf[nt]);
        }
    };

    const int TILES = K / 32;
    issue(0, 0);
    for (int t = 0; t < TILES; t++) {
        cp_wait<0>();
        __syncthreads();
        if (t + 1 < TILES) issue((t + 1) & 1, t + 1);
        compute(t & 1);
    }

#pragma unroll
    for (int mt = 0; mt < 2; mt++)
#pragma unroll
        for (int nt = 0; nt < 4; nt++)
#pragma unroll
            for (int half = 0; half < 2; half++) {
                int r = row0 + wm0 + mt * 16 + gid + half * 8;
                int c = col0 + wn0 + nt * 8 + 2 * tg;
                long off = (long)r * ldc + c;
                float v0 = acc[mt][nt][half * 2 + 0];
                float v1 = acc[mt][nt][half * 2 + 1];
                if (EPI == 2) {
                    float2 e = *(const float2*)(E + off);
                    v0 += e.x + bv[c];
                    v1 += e.y + bv[c + 1];
                } else if (EPI == 3) {
                    v0 += bv[c];
                    v1 += bv[c + 1];
                    v0 = 0.5f * v0 * (1.0f + erff(v0 * 0.70710678118654752f));
                    v1 = 0.5f * v1 * (1.0f + erff(v1 * 0.70710678118654752f));
                }
                float2 o; o.x = v0; o.y = v1;
                *(float2*)(C + off) = o;
            }
}

template <int EPI>
__global__ __launch_bounds__(256, 2)
void mma_gemm(const float* __restrict__ A, const float* __restrict__ Bm,
              float* __restrict__ C, const float* __restrict__ E,
              const float* __restrict__ bv,
              int K, int lda, int ldb, int ldc,
              long Ab, long Bb, long Cb) {
    extern __shared__ __align__(16) uint32_t smraw[];
    int z = blockIdx.z;
    A += (long)z * Ab;
    Bm += (long)z * Bb;
    long co = (long)z * Cb;
    gemm_core<EPI>(A, Bm, C + co, (EPI == 2) ? E + co : E, bv,
                   K, lda, ldb, ldc, blockIdx.y * 128, blockIdx.x * 64, smraw);
}

// merged kv + q launch: blockIdx.x [0,8) -> kv (N=512), [8,12) -> q (N=256)
__global__ __launch_bounds__(256, 2)
void kvq_gemm(const float* __restrict__ xn, const float* __restrict__ Wkv,
              float* __restrict__ kv,
              const float* __restrict__ xma, const float* __restrict__ Wq,
              float* __restrict__ qo) {
    extern __shared__ __align__(16) uint32_t smraw[];
    int row0 = blockIdx.y * 128;
    if (blockIdx.x < 8)
        gemm_core<0>(xn, Wkv, kv, nullptr, nullptr,
                     DIM, DIM, 2 * DIM, 2 * DIM, row0, blockIdx.x * 64, smraw);
    else
        gemm_core<0>(xma, Wq, qo, nullptr, nullptr,
                     DIM, DIM, DIM, DIM, row0, (blockIdx.x - 8) * 64, smraw);
}

// ---------------- fused flash attention, cp.async double-buffered K/V ----------------
__global__ __launch_bounds__(256)
void flash_kernel(const float* __restrict__ Qg, const float* __restrict__ KVg,
                  const __half* __restrict__ biasg, float* __restrict__ Og) {
    extern __shared__ uint32_t sm[];
    uint32_t* Qs = sm;                    // [128][68] tf32
    uint32_t* Ks = Qs + 128 * 68;         // [2][128*68] raw fp32
    uint32_t* Vs = Ks + 2 * 128 * 68;     // [2][128*72] raw fp32

    const int i0 = blockIdx.x * 128;
    const int h = blockIdx.y, b = blockIdx.z;
    const float* Qp = Qg + (long)b * NN_ * DIM + h * DH;
    const float* Kp = KVg + (long)b * NN_ * 2 * DIM + h * DH;
    const float* Vp = Kp + DIM;
    const __half* Bp = biasg + ((long)(b * HEADS + h)) * NN_ * NN_ + (long)i0 * NN_;

    const int tid = threadIdx.x, wid = tid >> 5, lane = tid & 31;
    const int gid = lane >> 2, tg = lane & 3;
    const int wm0 = wid * 16;

    auto issue_kv = [&](int buf, int j0) {
        uint32_t ks = smem_u32(Ks + buf * 128 * 68);
        uint32_t vs = smem_u32(Vs + buf * 128 * 72);
#pragma unroll
        for (int t = 0; t < 8; t++) {
            int q = tid + t * 256;
            int n = q >> 4, c4 = (q & 15) << 2;
            cpa16(ks + (n * 68 + c4) * 4, Kp + (long)(j0 + n) * (2 * DIM) + c4);
            cpa16(vs + (n * 72 + c4) * 4, Vp + (long)(j0 + n) * (2 * DIM) + c4);
        }
        cp_commit();
    };

    issue_kv(0, 0);

#pragma unroll
    for (int t = 0; t < 8; t++) {
        int q = tid + t * 256;
        int m = q >> 4, c4 = (q & 15) << 2;
        float4 v = *(const float4*)(Qp + (long)(i0 + m) * DIM + c4);
        *(uint4*)(Qs + m * 68 + c4) = cvt4(v);
    }

    float oacc[8][4];
#pragma unroll
    for (int i = 0; i < 8; i++)
#pragma unroll
        for (int j = 0; j < 4; j++) oacc[i][j] = 0.0f;
    float mi0 = -1e30f, mi1 = -1e30f, li0 = 0.0f, li1 = 0.0f;

    for (int t = 0; t < NN_ / 128; t++) {
        const int j0 = t * 128;
        const int buf = t & 1;
        cp_wait<0>();
        __syncthreads();
        if (t + 1 < NN_ / 128) issue_kv(buf ^ 1, j0 + 128);

        const uint32_t* kb = Ks + buf * 128 * 68;
        const uint32_t* vb = Vs + buf * 128 * 72;

        float s[16][4];
#pragma unroll
        for (int i = 0; i < 16; i++)
#pragma unroll
            for (int j = 0; j < 4; j++) s[i][j] = 0.0f;
#pragma unroll
        for (int ks = 0; ks < 64; ks += 8) {
            uint32_t a[4];
            const uint32_t* pa = Qs + (wm0 + gid) * 68 + ks + tg;
            a[0] = pa[0];
            a[1] = pa[8 * 68];
            a[2] = pa[4];
            a[3] = pa[8 * 68 + 4];
#pragma unroll
            for (int nt = 0; nt < 16; nt++) {
                const uint32_t* pb = kb + (nt * 8 + gid) * 68 + ks + tg;
                uint32_t bf[2] = { tfb(pb[0]), tfb(pb[4]) };
                mma_tf32(s[nt], a, bf);
            }
        }

        float rmax0 = -1e30f, rmax1 = -1e30f;
#pragma unroll
        for (int nt = 0; nt < 16; nt++) {
            long o0 = (long)(wm0 + gid) * NN_ + j0 + nt * 8 + 2 * tg;
            float2 e0 = __half22float2(*(const __half2*)(Bp + o0));
            float2 e1 = __half22float2(*(const __half2*)(Bp + o0 + 8 * NN_));
            s[nt][0] = fmaf(s[nt][0], SCALE, e0.x);
            s[nt][1] = fmaf(s[nt][1], SCALE, e0.y);
            s[nt][2] = fmaf(s[nt][2], SCALE, e1.x);
            s[nt][3] = fmaf(s[nt][3], SCALE, e1.y);
            rmax0 = fmaxf(rmax0, fmaxf(s[nt][0], s[nt][1]));
            rmax1 = fmaxf(rmax1, fmaxf(s[nt][2], s[nt][3]));
        }
        rmax0 = fmaxf(rmax0, __shfl_xor_sync(0xffffffffu, rmax0, 1));
        rmax0 = fmaxf(rmax0, __shfl_xor_sync(0xffffffffu, rmax0, 2));
        rmax1 = fmaxf(rmax1, __shfl_xor_sync(0xffffffffu, rmax1, 1));
        rmax1 = fmaxf(rmax1, __shfl_xor_sync(0xffffffffu, rmax1, 2));
        float mn0 = fmaxf(mi0, rmax0), mn1 = fmaxf(mi1, rmax1);
        float al0 = __expf(mi0 - mn0), al1 = __expf(mi1 - mn1);
        float rs0 = 0.0f, rs1 = 0.0f;
#pragma unroll
        for (int nt = 0; nt < 16; nt++) {
            s[nt][0] = __expf(s[nt][0] - mn0); rs0 += s[nt][0];
            s[nt][1] = __expf(s[nt][1] - mn0); rs0 += s[nt][1];
            s[nt][2] = __expf(s[nt][2] - mn1); rs1 += s[nt][2];
            s[nt][3] = __expf(s[nt][3] - mn1); rs1 += s[nt][3];
        }
        rs0 += __shfl_xor_sync(0xffffffffu, rs0, 1);
        rs0 += __shfl_xor_sync(0xffffffffu, rs0, 2);
        rs1 += __shfl_xor_sync(0xffffffffu, rs1, 1);
        rs1 += __shfl_xor_sync(0xffffffffu, rs1, 2);
        li0 = li0 * al0 + rs0;
        li1 = li1 * al1 + rs1;
        mi0 = mn0; mi1 = mn1;
#pragma unroll
        for (int nt = 0; nt < 8; nt++) {
            oacc[nt][0] *= al0; oacc[nt][1] *= al0;
            oacc[nt][2] *= al1; oacc[nt][3] *= al1;
        }

        const int src = (lane & ~3) | (tg >> 1);
        const bool odd = (tg & 1);
#pragma unroll
        for (int g = 0; g < 16; g++) {
            float f0 = __shfl_sync(0xffffffffu, s[g][0], src);
            float f1 = __shfl_sync(0xffffffffu, s[g][1], src);
            float f2 = __shfl_sync(0xffffffffu, s[g][0], src + 2);
            float f3 = __shfl_sync(0xffffffffu, s[g][1], src + 2);
            float h0 = __shfl_sync(0xffffffffu, s[g][2], src);
            float h1 = __shfl_sync(0xffffffffu, s[g][3], src);
            float h2 = __shfl_sync(0xffffffffu, s[g][2], src + 2);
            float h3 = __shfl_sync(0xffffffffu, s[g][3], src + 2);
            uint32_t pa4[4];
            pa4[0] = f2tf(odd ? f1 : f0);
            pa4[1] = f2tf(odd ? h1 : h0);
            pa4[2] = f2tf(odd ? f3 : f2);
            pa4[3] = f2tf(odd ? h3 : h2);
#pragma unroll
            for (int nt = 0; nt < 8; nt++) {
                const uint32_t* pb = vb + (g * 8 + tg) * 72 + nt * 8 + gid;
                uint32_t bf[2] = { tfb(pb[0]), tfb(pb[4 * 72]) };
                mma_tf32(oacc[nt], pa4, bf);
            }
        }
    }

    float iv0 = 1.0f / li0, iv1 = 1.0f / li1;
#pragma unroll
    for (int nt = 0; nt < 8; nt++) {
        long off = ((long)b * NN_ + i0 + wm0 + gid) * DIM + h * DH + nt * 8 + 2 * tg;
        float2 o0; o0.x = oacc[nt][0] * iv0; o0.y = oacc[nt][1] * iv0;
        float2 o1; o1.x = oacc[nt][2] * iv1; o1.y = oacc[nt][3] * iv1;
        *(float2*)(Og + off) = o0;
        *(float2*)(Og + off + 8 * DIM) = o1;
    }
}

// ---------------- prep: add_attn(fp16) ; G = softmax(mean(b0)*mean(b1)) ----------
__global__ __launch_bounds__(256)
void prep_kernel(const float* __restrict__ ab) {
    __shared__ float sh[32];
    int b = blockIdx.x >> 10;
    int i = blockIdx.x & 1023;
    const long BHNN = (long)BB * HEADS * NN_ * NN_;
    int tid = threadIdx.x;
    int j4 = tid * 4;
    float4 sa = make_float4(0, 0, 0, 0), sb = make_float4(0, 0, 0, 0);
#pragma unroll
    for (int h = 0; h < HEADS; h++) {
        long o = (((long)(b * HEADS + h) * NN_) + i) * NN_ + j4;
        float4 a0 = *(const float4*)(ab + o);
        float4 a1 = *(const float4*)(ab + BHNN + o);
        sa.x += a0.x; sa.y += a0.y; sa.z += a0.z; sa.w += a0.w;
        sb.x += a1.x; sb.y += a1.y; sb.z += a1.z; sb.w += a1.w;
        union { __half2 h2[2]; uint2 u; } pk;
        pk.h2[0] = __floats2half2_rn(a0.x + a1.x, a0.y + a1.y);
        pk.h2[1] = __floats2half2_rn(a0.z + a1.z, a0.w + a1.w);
        *(uint2*)(&g_bias[o]) = pk.u;
    }
    float val[4];
    val[0] = (sa.x * 0.25f) * (sb.x * 0.25f);
    val[1] = (sa.y * 0.25f) * (sb.y * 0.25f);
    val[2] = (sa.z * 0.25f) * (sb.z * 0.25f);
    val[3] = (sa.w * 0.25f) * (sb.w * 0.25f);
    float m = fmaxf(fmaxf(val[0], val[1]), fmaxf(val[2], val[3]));
    m = block_max(m, sh);
    float s = 0.0f;
#pragma unroll
    for (int t = 0; t < 4; t++) { val[t] = __expf(val[t] - m); s += val[t]; }
    s = block_sum(s, sh);
    float inv = 1.0f / s;
    long rowo = ((long)(b * NN_ + i)) * NN_ + j4;
    float4 g4; g4.x = val[0] * inv; g4.y = val[1] * inv; g4.z = val[2] * inv; g4.w = val[3] * inv;
    *(float4*)(g_G + rowo) = g4;
}

// ---------------- LayerNorm: one warp/row, one-pass (sum+sumsq), interleaved shuffles ------
__device__ __forceinline__ void ln_row(const float* __restrict__ in, float* __restrict__ out,
                                       const float* __restrict__ g, const float* __restrict__ bt,
                                       long row, int lane, int relu) {
    const float* p = in + row * DIM + lane * 8;
    float4 v0 = *(const float4*)p;
    float4 v1 = *(const float4*)(p + 4);
    float s = v0.x + v0.y + v0.z + v0.w + v1.x + v1.y + v1.z + v1.w;
    float q = v0.x * v0.x + v0.y * v0.y + v0.z * v0.z + v0.w * v0.w
            + v1.x * v1.x + v1.y * v1.y + v1.z * v1.z + v1.w * v1.w;
#pragma unroll
    for (int o = 16; o; o >>= 1) {
        s += __shfl_xor_sync(0xffffffffu, s, o);
        q += __shfl_xor_sync(0xffffffffu, q, o);
    }
    float mean = s * (1.0f / DIM);
    float var = q * (1.0f / DIM) - mean * mean;
    float rstd = rsqrtf(var + EPS);
    const float* gp = g + lane * 8;
    const float* bp = bt + lane * 8;
    float4 g0 = *(const float4*)gp, g1 = *(const float4*)(gp + 4);
    float4 b0 = *(const float4*)bp, b1 = *(const float4*)(bp + 4);
    float o8[8];
    o8[0] = (v0.x - mean) * rstd * g0.x + b0.x; o8[1] = (v0.y - mean) * rstd * g0.y + b0.y;
    o8[2] = (v0.z - mean) * rstd * g0.z + b0.z; o8[3] = (v0.w - mean) * rstd * g0.w + b0.w;
    o8[4] = (v1.x - mean) * rstd * g1.x + b1.x; o8[5] = (v1.y - mean) * rstd * g1.y + b1.y;
    o8[6] = (v1.z - mean) * rstd * g1.z + b1.z; o8[7] = (v1.w - mean) * rstd * g1.w + b1.w;
    if (relu) {
#pragma unroll
        for (int t = 0; t < 8; t++) o8[t] = fmaxf(o8[t], 0.0f);
    }
    float* po = out + row * DIM + lane * 8;
    float4 r0; r0.x = o8[0]; r0.y = o8[1]; r0.z = o8[2]; r0.w = o8[3];
    float4 r1; r1.x = o8[4]; r1.y = o8[5]; r1.z = o8[6]; r1.w = o8[7];
    *(float4*)po = r0;
    *(float4*)(po + 4) = r1;
}

__global__ __launch_bounds__(256)
void ln_one(const float* __restrict__ in, float* __restrict__ out,
            const float* __restrict__ g, const float* __restrict__ bt) {
    int w = threadIdx.x >> 5, lane = threadIdx.x & 31;
    ln_row(in, out, g, bt, (long)blockIdx.x * 8 + w, lane, 0);
}

// merged: blocks [0,nA) -> LN+relu on A (in-place semantics ok), blocks [nA,2nA) -> LN on B
__global__ __launch_bounds__(256)
void ln_fused(const float* __restrict__ inA, float* __restrict__ outA,
              const float* __restrict__ gA, const float* __restrict__ bA,
              const float* __restrict__ inB, float* __restrict__ outB,
              const float* __restrict__ gB, const float* __restrict__ bB, int nA) {
    int w = threadIdx.x >> 5, lane = threadIdx.x & 31;
    int bid = blockIdx.x;
    if (bid < nA)
        ln_row(inA, outA, gA, bA, (long)bid * 8 + w, lane, 1);
    else
        ln_row(inB, outB, gB, bB, (long)(bid - nA) * 8 + w, lane, 0);
}

// ---------------- host ----------------
extern "C" void kernel_launch(void* const* d_in, const int* in_sizes, int n_in,
                              void* d_out, int out_size) {
    const float* x_in   = (const float*)d_in[0];
    const float* abias  = (const float*)d_in[1];
    const float* ln1_g  = (const float*)d_in[2];
    const float* ln1_b  = (const float*)d_in[3];
    const float* Wkv    = (const float*)d_in[4];
    const float* Wq     = (const float*)d_in[5];
    const float* Wo     = (const float*)d_in[6];
    const float* bo     = (const float*)d_in[7];
    const float* ln2_g  = (const float*)d_in[8];
    const float* ln2_b  = (const float*)d_in[9];
    const float* W1     = (const float*)d_in[10];
    const float* b1     = (const float*)d_in[11];
    const float* W2     = (const float*)d_in[12];
    const float* b2     = (const float*)d_in[13];
    const float* Wg     = (const float*)d_in[14];
    const float* lng_g  = (const float*)d_in[15];
    const float* lng_b  = (const float*)d_in[16];
    float* out = (float*)d_out;

    float *px, *pxn, *pxma, *pq, *pkv, *pao, *pG, *pff;
    __half* pbias;
    cudaGetSymbolAddress((void**)&px, g_x);
    cudaGetSymbolAddress((void**)&pxn, g_xn);
    cudaGetSymbolAddress((void**)&pxma, g_xma);
    cudaGetSymbolAddress((void**)&pq, g_q);
    cudaGetSymbolAddress((void**)&pkv, g_kv);
    cudaGetSymbolAddress((void**)&pao, g_ao);
    cudaGetSymbolAddress((void**)&pG, g_G);
    cudaGetSymbolAddress((void**)&pbias, g_bias);
    cudaGetSymbolAddress((void**)&pff, g_ff);

    const int ROWS = BB * NN_;           // 4096
    const long ND = (long)NN_ * DIM;
    dim3 blk(256);

    const int SM_G = SM_WORDS * 4;                                    // 55296
    const int SM_FL = (128 * 68 + 2 * 128 * 68 + 2 * 128 * 72) * 4;   // 178176
    cudaFuncSetAttribute(mma_gemm<0>, cudaFuncAttributeMaxDynamicSharedMemorySize, SM_G);
    cudaFuncSetAttribute(mma_gemm<2>, cudaFuncAttributeMaxDynamicSharedMemorySize, SM_G);
    cudaFuncSetAttribute(mma_gemm<3>, cudaFuncAttributeMaxDynamicSharedMemorySize, SM_G);
    cudaFuncSetAttribute(kvq_gemm, cudaFuncAttributeMaxDynamicSharedMemorySize, SM_G);
    cudaFuncSetAttribute(flash_kernel, cudaFuncAttributeMaxDynamicSharedMemorySize, SM_FL);

    prep_kernel<<<BB * NN_, blk>>>(abias);

    for (int l = 0; l < DEPTH; l++) {
        const float* xcur = (l == 0) ? x_in : px;
        // GX = G @ x -> g_xn   [per b: 1024x256, K=1024]
        mma_gemm<0><<<dim3(DIM / 64, NN_ / 128, BB), blk, SM_G>>>(
            pG, xcur, pxn, nullptr, nullptr,
            NN_, NN_, DIM, DIM, (long)NN_ * NN_, ND, ND);
        // x_ma_pre = GX @ Wg -> g_xma
        mma_gemm<0><<<dim3(DIM / 64, ROWS / 128, 1), blk, SM_G>>>(
            pxn, Wg, pxma, nullptr, nullptr,
            DIM, DIM, DIM, DIM, 0, 0, 0);
        // merged: x_ma = relu(LN(x_ma)) in place ; xn = LN(x)
        ln_fused<<<ROWS / 4, blk>>>(pxma, pxma, lng_g, lng_b,
                                    xcur, pxn, ln1_g + l * DIM, ln1_b + l * DIM, ROWS / 8);
        // merged kv + q (384 blocks)
        kvq_gemm<<<dim3(12, ROWS / 128, 1), blk, SM_G>>>(
            pxn, Wkv + (long)l * DIM * 2 * DIM, pkv,
            pxma, Wq + (long)l * DIM * DIM, pq);
        // fused attention -> g_ao
        flash_kernel<<<dim3(NN_ / 128, HEADS, BB), blk, SM_FL>>>(pq, pkv, pbias, pao);
        // x = x + out @ Wo[l] + bo[l]
        mma_gemm<2><<<dim3(DIM / 64, ROWS / 128, 1), blk, SM_G>>>(
            pao, Wo + (long)l * DIM * DIM, px, xcur, bo + l * DIM,
            DIM, DIM, DIM, DIM, 0, 0, 0);
        // xn2 = LN(x)
        ln_one<<<ROWS / 8, blk>>>(px, pxn, ln2_g + l * DIM, ln2_b + l * DIM);
        // ff = gelu(xn2 @ W1[l] + b1[l])   (512 blocks)
        mma_gemm<3><<<dim3(MLP / 64, ROWS / 128, 1), blk, SM_G>>>(
            pxn, W1 + (long)l * DIM * MLP, pff, nullptr, b1 + l * MLP,
            DIM, DIM, MLP, MLP, 0, 0, 0);
        // x = x + ff @ W2[l] + b2[l]  (last layer -> d_out)
        float* cdst = (l == DEPTH - 1) ? out : px;
        mma_gemm<2><<<dim3(DIM / 64, ROWS / 128, 1), blk, SM_G>>>(
            pff, W2 + (long)l * MLP * DIM, cdst, px, b2 + l * DIM,
            MLP, MLP, DIM, DIM, 0, 0, 0);
    }
}